// round 14
// baseline (speedup 1.0000x reference)
#include <cuda_runtime.h>
#include <cuda_bf16.h>
#include <math.h>
#include <cstdint>

// ===========================================================================
// DARM on GB300 (base sm_103 ISA): split-bf16 (3-term) mma.sync implicit-GEMM
// convs + fp32 head conv (split-output) + SE + per-pixel dynamic filtering.
// B=8, C=3, H=W=128, F=128, S=8, K=72.
// Activation layout (load-native): act[b][g][pl][y][x][q], q=0..7,
//   word q = packed(bf16 ci0 | bf16 ci1<<16), ci0=g*16+p, ci1=ci0+8,
//   p=(q>>1)+((q&1)<<2), pl = hi/lo split plane.
// R14: BALANCED tail conv (Cout=72): lower-m warps cover mblks 0..2 (co 0-47),
//   upper-m warps cover mblks 3..4 (co 48-79) -> max warp work 3 mt-slots
//   (was 4); barrier-bound chunk time scales ~3/4.
// ===========================================================================

#define B_ 8
#define F_ 128
#define K_ 72
#define WS 147456         // words per repacked conv weight set (24 * 6144)

__device__ unsigned g_A[16777216];           // 64 MiB  (split act / ping)
__device__ unsigned g_B[16777216];           // 64 MiB  (split act / pong; fp32 tail out)
__device__ float    g_mean[B_ * F_];
__device__ float    g_scl[B_ * F_];
__device__ unsigned g_Wt[5 * WS];            // fragment-major repacked weights
__device__ unsigned g_Wts[B_ * WS];          // per-batch SE-scaled weights

// ---------------------------------------------------------------------------
// helpers
// ---------------------------------------------------------------------------
__device__ __forceinline__ uint32_t smem_u32(const void* p) {
    uint32_t a;
    asm("{ .reg .u64 t; cvta.to.shared.u64 t, %1; cvt.u32.u64 %0, t; }" : "=r"(a) : "l"(p));
    return a;
}
__device__ __forceinline__ void cpa16(uint32_t d, const void* s) {
    asm volatile("cp.async.cg.shared.global [%0], [%1], 16;" :: "r"(d), "l"(s) : "memory");
}
__device__ __forceinline__ void cpa16z(uint32_t d, const void* s, int sz) {
    asm volatile("cp.async.cg.shared.global [%0], [%1], 16, %2;" :: "r"(d), "l"(s), "r"(sz) : "memory");
}
#define CP_COMMIT() asm volatile("cp.async.commit_group;" ::: "memory")
#define CP_WAIT1()  asm volatile("cp.async.wait_group 1;" ::: "memory")

#define MMA_BF16(d, a, bb) \
    asm volatile("mma.sync.aligned.m16n8k16.row.col.f32.bf16.bf16.f32 " \
        "{%0,%1,%2,%3},{%4,%5,%6,%7},{%8,%9},{%0,%1,%2,%3};" \
        : "+f"((d)[0]), "+f"((d)[1]), "+f"((d)[2]), "+f"((d)[3]) \
        : "r"((a)[0]), "r"((a)[1]), "r"((a)[2]), "r"((a)[3]), "r"((bb)[0]), "r"((bb)[1]))

__device__ __forceinline__ uint32_t bfb(float v) {
    return (uint32_t)__bfloat16_as_ushort(__float2bfloat16(v));
}
__device__ __forceinline__ float bff(uint32_t b) { return __uint_as_float(b << 16); }
__device__ __forceinline__ void split2(float v, uint32_t& h, uint32_t& l) {
    h = bfb(v);
    l = bfb(v - bff(h));
}

// ---------------------------------------------------------------------------
// Weight repack (ALL 5 convs, fragment-major).
// grid (576, 5), block 128.
// ---------------------------------------------------------------------------
__global__ void repack_all_kernel(const float* __restrict__ w0, const float* __restrict__ w1,
                                  const float* __restrict__ w2, const float* __restrict__ w3,
                                  const float* __restrict__ w4, unsigned* __restrict__ wt)
{
    const float* w;
    int Cout = 128;
    switch (blockIdx.y) {
        case 0: w = w0; break;
        case 1: w = w1; break;
        case 2: w = w2; break;
        case 3: w = w3; break;
        default: w = w4; Cout = 72; break;
    }
    int idx = blockIdx.x * 128 + threadIdx.x;        // 0..73727
    int w_   = idx & 3;
    int lane = (idx >> 2) & 31;
    int mblk = (idx >> 7) & 7;
    int rest = idx >> 10;                            // t*3 + kx
    int kx = rest % 3;
    int t  = rest / 3;
    int cg = t / 3, ky = t - cg * 3;
    int p  = (lane & 3) + ((w_ >> 1) << 2);
    int co = mblk * 16 + (lane >> 2) + ((w_ & 1) << 3);
    int ci0 = cg * 16 + p, ci1 = ci0 + 8;
    float v0 = 0.f, v1 = 0.f;
    if (co < Cout) {
        v0 = w[co * 1152 + ci0 * 9 + ky * 3 + kx];
        v1 = w[co * 1152 + ci1 * 9 + ky * 3 + kx];
    }
    uint32_t h0, l0, h1, l1;
    split2(v0, h0, l0); split2(v1, h1, l1);
    unsigned* o = wt + (size_t)blockIdx.y * WS + t * 6144;
    int base = (kx * 8 + mblk) * 128 + lane * 4 + w_;
    o[base]        = h0 | (h1 << 16);
    o[base + 3072] = l0 | (l1 << 16);
}

// ---------------------------------------------------------------------------
// SE weight-scale (fragment-major indexing).
// grid (576, 8), block 128.
// ---------------------------------------------------------------------------
__global__ void scale_w_kernel(const unsigned* __restrict__ wt, const float* __restrict__ scl,
                               unsigned* __restrict__ wts)
{
    int b = blockIdx.y;
    int idx = blockIdx.x * 128 + threadIdx.x;
    int w_   = idx & 3;
    int lane = (idx >> 2) & 31;
    int mblk = (idx >> 7) & 7;
    int rest = idx >> 10;
    int kx = rest % 3;
    int t  = rest / 3;
    int cg = t / 3;
    int p  = (lane & 3) + ((w_ >> 1) << 2);
    int ci0 = cg * 16 + p, ci1 = ci0 + 8;
    int base = t * 6144 + (kx * 8 + mblk) * 128 + lane * 4 + w_;
    unsigned wh = wt[base], wl = wt[base + 3072];
    float s0 = scl[b * 128 + ci0];
    float s1 = scl[b * 128 + ci1];
    float v0 = (bff(wh & 0xffffu) + bff(wl & 0xffffu)) * s0;
    float v1 = (bff(wh >> 16) + bff(wl >> 16)) * s1;
    uint32_t h0, l0, h1, l1;
    split2(v0, h0, l0); split2(v1, h1, l1);
    unsigned* o = wts + (size_t)b * WS;
    o[base]        = h0 | (h1 << 16);
    o[base + 3072] = l0 | (l1 << 16);
}

// ---------------------------------------------------------------------------
// split-bf16 mma conv, Cin=128. CTA: M=128 co x N=128 px (2 rows x 64 cols).
// 8 warps (2m x 4n), warp tile 64x32 -> mt<=4, nf=4 m16n8k16 frags.
// K = 1152: 24 chunks (cg,ky) x 3 kx x 16 ci. 3 MMAs (hi*hi,hi*lo,lo*hi).
// tailMode (Cout=72): lower warps mblks 0..2 (mtN=3), upper mblks 3..4
//   (mtN=2, mb0=3) -> balanced, max warp work 3 mt-slots.
// smem b32: A bufs 3 x 6144 (fragment-major)          @ 0
//           B bufs 2 x 4224 ([pl][rs4][xs66][q8])     @ 18432
// Pipeline: 2-chunk slack, wait_group 1, one commit per iteration.
// grid (128 = 64 rowpairs x 2 colhalves, 8 batch), block 256, 2 CTAs/SM.
// ---------------------------------------------------------------------------
#define CONV_SMEM ((3 * 6144 + 2 * 4224) * 4)   // 107520 B

__global__ __launch_bounds__(256, 2)
void conv_mma_kernel(const unsigned* __restrict__ actin, const unsigned* __restrict__ wt,
                     const float* __restrict__ bias, void* __restrict__ outp,
                     int Cout, int doRelu, int splitOut, int perBatchW, int tailMode)
{
    extern __shared__ unsigned sm32[];
    const uint32_t sb = smem_u32(sm32);

    const int tid  = threadIdx.x;
    const int wid  = tid >> 5;                  // 0..7
    const int lane = tid & 31;
    const int tid4 = lane & 3;
    const int grp  = lane >> 2;
    const int hi   = wid >> 2;                  // 0 = lower-m, 1 = upper-m
    const int n0 = (wid & 3) * 32;              // 0..96
    const int lane4 = lane * 4;
    // balanced m-partition: normal = {0..3 | 4..7}; tail = {0..2 | 3..4}
    const int mb0 = tailMode ? (hi ? 3 : 0) : hi * 4;
    const int mtN = tailMode ? (hi ? 2 : 3) : 4;
    const int m0  = mb0 * 16;
    const int b  = blockIdx.y;
    const int rp = blockIdx.x >> 1;             // row-pair 0..63
    const int ch = blockIdx.x & 1;              // col-half
    const int y0 = rp * 2;
    const int x0 = ch * 64;

    const unsigned* wtb = wt + (perBatchW ? (size_t)b * WS : 0);

    // per-thread B fragment bases: off = r*528 + xloc*8 + tid4*2 (+ky*528 +kx*8)
    int nbase[4];
#pragma unroll
    for (int nf = 0; nf < 4; nf++) {
        int n = n0 + nf * 8 + grp;
        nbase[nf] = (n >> 6) * 528 + (n & 63) * 8 + tid4 * 2;
    }

    float d[4][4][4];
#pragma unroll
    for (int mt = 0; mt < 4; mt++)
#pragma unroll
        for (int nf = 0; nf < 4; nf++)
#pragma unroll
            for (int i = 0; i < 4; i++) d[mt][nf][i] = 0.f;

    auto loadA = [&](int t, int buf) {
        const unsigned* src = wtb + t * 6144;
        const uint32_t dst = sb + (uint32_t)buf * 24576u;
#pragma unroll
        for (int i = tid; i < 1536; i += 256)
            cpa16(dst + (uint32_t)i * 16u, src + i * 4);
    };
    // B: 1056 contiguous cpa16. i = ((pl*4+rs)*66+xs)*2+qh
    auto loadB = [&](int cg, int buf) {
        const uint32_t dst = sb + 73728u + (buf ? 16896u : 0u);
        const unsigned* basep = actin + ((size_t)b * 8 + cg) * 262144;
        for (int i = tid; i < 1056; i += 256) {
            int qh = i & 1, r = i >> 1;          // r = (pl*4+rs)*66 + xs
            int xs = r % 66;
            int r2 = r / 66;                     // pl*4 + rs
            int rs = r2 & 3, pl = r2 >> 2;
            int y = y0 - 1 + rs, xi = x0 - 1 + xs;
            bool ok = ((unsigned)y < 128u) && ((unsigned)xi < 128u);
            const unsigned* src = basep + pl * 131072
                                + (ok ? ((y * 128 + xi) * 8) : 0) + qh * 4;
            uint32_t doff = (uint32_t)(pl * 2112 + rs * 528 + xs * 8 + qh * 4) * 4u;
            cpa16z(dst + doff, src, ok ? 16 : 0);
        }
    };

    // prologue: G0 = {A0, B0}, G1 = {A1}
    loadB(0, 0);
    loadA(0, 0);
    CP_COMMIT();
    loadA(1, 1);
    CP_COMMIT();

    for (int t = 0; t < 24; ++t) {
        const int cg = t / 3;
        const int ky = t - cg * 3;
        CP_WAIT1();                      // G_t complete (G_{t+1} may be in flight)
        __syncthreads();
        const int tn = t + 2;
        if (tn < 24) {
            loadA(tn, tn % 3);
            if (tn % 3 == 0) loadB(tn / 3, (tn / 3) & 1);
        }
        CP_COMMIT();                     // one group per iteration (may be empty)

        const unsigned* As = sm32 + (t % 3) * 6144;
        const unsigned* Bs = sm32 + 18432 + (cg & 1) * 4224;
        const int kyo = ky * 528;

#pragma unroll
        for (int kx = 0; kx < 3; ++kx) {
            uint32_t ah[4][4], al[4][4];
#pragma unroll
            for (int mt = 0; mt < 4; mt++) {
                if (mt < mtN) {
                    int ab = (kx * 8 + mb0 + mt) * 128 + lane4;
                    *(uint4*)ah[mt] = *(const uint4*)(As + ab);
                    *(uint4*)al[mt] = *(const uint4*)(As + ab + 3072);
                }
            }
            uint32_t bh[4][2], bl[4][2];
#pragma unroll
            for (int nf = 0; nf < 4; nf++) {
                int off = nbase[nf] + kyo + kx * 8;
                *(uint2*)bh[nf] = *(const uint2*)(Bs + off);
                *(uint2*)bl[nf] = *(const uint2*)(Bs + off + 2112);
            }
#pragma unroll
            for (int nf = 0; nf < 4; nf++)
#pragma unroll
                for (int mt = 0; mt < 4; mt++)
                    if (mt < mtN) MMA_BF16(d[mt][nf], ah[mt], bh[nf]);
#pragma unroll
            for (int nf = 0; nf < 4; nf++)
#pragma unroll
                for (int mt = 0; mt < 4; mt++)
                    if (mt < mtN) MMA_BF16(d[mt][nf], ah[mt], bl[nf]);
#pragma unroll
            for (int nf = 0; nf < 4; nf++)
#pragma unroll
                for (int mt = 0; mt < 4; mt++)
                    if (mt < mtN) MMA_BF16(d[mt][nf], al[mt], bh[nf]);
        }
    }

    // ---- epilogue ----
    if (splitOut) {
        unsigned* outu = (unsigned*)outp;
#pragma unroll
        for (int mt = 0; mt < 4; mt++) {
            if (mt >= mtN) continue;
            const int co0 = m0 + mt * 16 + grp;       // p = grp (0..7)
            const int g = co0 >> 4;
            const int q = 2 * (grp & 3) + (grp >> 2);
            const float bv0 = bias[co0], bv1 = bias[co0 + 8];
            const size_t bhi = (((size_t)b * 8 + g) * 2 + 0) * 131072;
            const size_t blo = bhi + 131072;
#pragma unroll
            for (int nf = 0; nf < 4; nf++) {
                const int n = n0 + nf * 8 + 2 * tid4;
                const int pix = (y0 + (n >> 6)) * 128 + x0 + (n & 63);
                float v0 = d[mt][nf][0] + bv0, v1 = d[mt][nf][1] + bv0;
                float v2 = d[mt][nf][2] + bv1, v3 = d[mt][nf][3] + bv1;
                if (doRelu) {
                    v0 = fmaxf(v0, 0.f); v1 = fmaxf(v1, 0.f);
                    v2 = fmaxf(v2, 0.f); v3 = fmaxf(v3, 0.f);
                }
                uint32_t h0, l0, h1, l1, h2, l2, h3, l3;
                split2(v0, h0, l0); split2(v1, h1, l1);
                split2(v2, h2, l2); split2(v3, h3, l3);
                outu[bhi + (size_t)pix * 8 + q]       = h0 | (h2 << 16);
                outu[bhi + (size_t)(pix + 1) * 8 + q] = h1 | (h3 << 16);
                outu[blo + (size_t)pix * 8 + q]       = l0 | (l2 << 16);
                outu[blo + (size_t)(pix + 1) * 8 + q] = l1 | (l3 << 16);
            }
        }
    } else {
        float* outf = (float*)outp;
#pragma unroll
        for (int mt = 0; mt < 4; mt++) {
            if (mt >= mtN) continue;
            const int co0 = m0 + mt * 16 + grp;
            const int co1 = co0 + 8;
            const float bv0 = (co0 < Cout) ? bias[co0] : 0.f;
            const float bv1 = (co1 < Cout) ? bias[co1] : 0.f;
#pragma unroll
            for (int nf = 0; nf < 4; nf++) {
                const int n = n0 + nf * 8 + 2 * tid4;
                const int y = y0 + (n >> 6), x = x0 + (n & 63);
                if (co0 < Cout) {
                    float v0 = d[mt][nf][0] + bv0, v1 = d[mt][nf][1] + bv0;
                    if (doRelu) { v0 = fmaxf(v0, 0.f); v1 = fmaxf(v1, 0.f); }
                    *(float2*)(outf + (((size_t)b * Cout + co0) * 128 + y) * 128 + x)
                        = make_float2(v0, v1);
                }
                if (co1 < Cout) {
                    float v2 = d[mt][nf][2] + bv1, v3 = d[mt][nf][3] + bv1;
                    if (doRelu) { v2 = fmaxf(v2, 0.f); v3 = fmaxf(v3, 0.f); }
                    *(float2*)(outf + (((size_t)b * Cout + co1) * 128 + y) * 128 + x)
                        = make_float2(v2, v3);
                }
            }
        }
    }
}

// ---------------------------------------------------------------------------
// fp32 head conv (Cin=3, Cout=128), writes the q-ordered SPLIT layout.
// ---------------------------------------------------------------------------
__global__ __launch_bounds__(256, 2)
void conv3x3_head_kernel(const float* __restrict__ in, const float* __restrict__ w,
                         const float* __restrict__ bias, unsigned* __restrict__ out)
{
    const int Cin = 3;
    __shared__ float s_in[3 * 18 * 18];
    __shared__ float s_w[32 * 3 * 9];
    const int tid = threadIdx.x;
    const int b   = blockIdx.z;
    const int coG = blockIdx.y;
    const int ty  = blockIdx.x >> 3;
    const int tx  = blockIdx.x & 7;
    const int y0 = ty * 16, x0 = tx * 16;
    const int co_base = tid >> 5;              // 0..7 = p
    const int pid = tid & 31;
    const int y  = pid >> 1;
    const int xb = (pid & 1) * 8;

    float acc[4][8];
#pragma unroll
    for (int j = 0; j < 4; j++)
#pragma unroll
        for (int p = 0; p < 8; p++) acc[j][p] = 0.f;

    for (int idx = tid; idx < 3 * 324; idx += 256) {
        int ci = idx / 324;
        int r  = idx - ci * 324;
        int iy = r / 18, ix = r - iy * 18;
        int gy = y0 - 1 + iy, gx = x0 - 1 + ix;
        float v = 0.f;
        if ((unsigned)gy < 128u && (unsigned)gx < 128u)
            v = in[((b * Cin + ci) * 128 + gy) * 128 + gx];
        s_in[idx] = v;
    }
    for (int idx = tid; idx < 32 * 27; idx += 256) {
        int l = idx / 27;
        int r = idx - l * 27;
        s_w[idx] = w[(coG * 32 + l) * 27 + r];
    }
    __syncthreads();

#pragma unroll
    for (int ci = 0; ci < 3; ci++) {
#pragma unroll
        for (int ky = 0; ky < 3; ky++) {
            float r[10];
            const float* row = &s_in[ci * 324 + (y + ky) * 18 + xb];
#pragma unroll
            for (int i = 0; i < 10; i++) r[i] = row[i];
#pragma unroll
            for (int kx = 0; kx < 3; kx++) {
#pragma unroll
                for (int j = 0; j < 4; j++) {
                    float wv = s_w[(co_base + j * 8) * 27 + ci * 9 + ky * 3 + kx];
#pragma unroll
                    for (int p = 0; p < 8; p++)
                        acc[j][p] = fmaf(wv, r[p + kx], acc[j][p]);
                }
            }
        }
    }

    float bv[4];
#pragma unroll
    for (int j = 0; j < 4; j++) bv[j] = bias[coG * 32 + co_base + j * 8];

    const int q = 2 * (co_base & 3) + (co_base >> 2);
    const int g0 = 2 * coG, g1 = 2 * coG + 1;
    const size_t b0h = (((size_t)b * 8 + g0) * 2 + 0) * 131072;
    const size_t b1h = (((size_t)b * 8 + g1) * 2 + 0) * 131072;
#pragma unroll
    for (int p = 0; p < 8; p++) {
        size_t pix8 = (size_t)((y0 + y) * 128 + x0 + xb + p) * 8 + q;
        uint32_t h0, q0, h1, q1, h2, q2, h3, q3;
        split2(acc[0][p] + bv[0], h0, q0);
        split2(acc[1][p] + bv[1], h1, q1);
        split2(acc[2][p] + bv[2], h2, q2);
        split2(acc[3][p] + bv[3], h3, q3);
        out[b0h + pix8]          = h0 | (h1 << 16);
        out[b0h + 131072 + pix8] = q0 | (q1 << 16);
        out[b1h + pix8]          = h2 | (h3 << 16);
        out[b1h + 131072 + pix8] = q2 | (q3 << 16);
    }
}

// ---------------------------------------------------------------------------
// SE pool on q-ordered split activations. One block per (b,g).
// grid 64, block 256.
// ---------------------------------------------------------------------------
__global__ void se_pool_split_kernel(const unsigned* __restrict__ act, float* __restrict__ mean)
{
    const int bg = blockIdx.x;                 // b*8 + g
    const int b = bg >> 3, g = bg & 7;
    const uint4* basep = (const uint4*)(act + (size_t)bg * 262144);
    const int t = threadIdx.x;

    float s[8];
#pragma unroll
    for (int j = 0; j < 8; j++) s[j] = 0.f;

    for (int k = 0; k < 256; k++) {
        uint4 v = basep[t + k * 256];
        s[0] += bff(v.x & 0xffffu); s[1] += bff(v.x >> 16);
        s[2] += bff(v.y & 0xffffu); s[3] += bff(v.y >> 16);
        s[4] += bff(v.z & 0xffffu); s[5] += bff(v.z >> 16);
        s[6] += bff(v.w & 0xffffu); s[7] += bff(v.w >> 16);
    }
#pragma unroll
    for (int o = 16; o >= 2; o >>= 1)
#pragma unroll
        for (int j = 0; j < 8; j++) s[j] += __shfl_xor_sync(0xffffffffu, s[j], o);

    __shared__ float cs[16];
    if (t < 16) cs[t] = 0.f;
    __syncthreads();
    int lane = t & 31;
    if (lane < 2) {
#pragma unroll
        for (int j = 0; j < 8; j++) atomicAdd(&cs[lane * 8 + j], s[j]);
    }
    __syncthreads();
    if (t < 16) {
        int qh = t >> 3, jh = t & 7;
        int j = jh >> 1, half = jh & 1;
        int q = qh * 4 + j;
        int p = (q >> 1) + ((q & 1) << 2);
        int c = g * 16 + p + half * 8;
        mean[b * 128 + c] = cs[t] * (1.f / 16384.f);
    }
}

__global__ void se_fc_kernel(const float* __restrict__ mean,
                             const float* __restrict__ w1, const float* __restrict__ b1,
                             const float* __restrict__ w2, const float* __restrict__ b2,
                             float* __restrict__ scl)
{
    __shared__ float smn[8][128];
    __shared__ float s1[8][8];
    int t = threadIdx.x;
    smn[t >> 7][t & 127] = mean[t];
    __syncthreads();
    if (t < 64) {
        int bb = t >> 3, j = t & 7;
        float a = b1[j];
#pragma unroll 4
        for (int c = 0; c < 128; c++) a = fmaf(w1[j * 128 + c], smn[bb][c], a);
        s1[bb][j] = fmaxf(a, 0.f);
    }
    __syncthreads();
    int bb = t >> 7, co = t & 127;
    float a = b2[co];
#pragma unroll
    for (int j = 0; j < 8; j++) a = fmaf(w2[co * 8 + j], s1[bb][j], a);
    scl[t] = 1.f / (1.f + expf(-a));
}

// ---------------------------------------------------------------------------
// Dynamic filtering (unchanged)
// ---------------------------------------------------------------------------
__global__ __launch_bounds__(256)
void dynfilter_kernel(const float* __restrict__ x, const float* __restrict__ wgt,
                      const float* __restrict__ basis, float* __restrict__ out)
{
    __shared__ float kb[K_ * 25];
    for (int i = threadIdx.x; i < K_ * 25; i += 256) kb[i] = basis[i];
    __syncthreads();
    int b = blockIdx.y;
    int y = blockIdx.x * 2 + (threadIdx.x >> 7);
    int xc = threadIdx.x & 127;
    float e[25];
#pragma unroll
    for (int p = 0; p < 25; p++) e[p] = 0.f;
    for (int k = 0; k < K_; k++) {
        float wv = wgt[((b * K_ + k) * 128 + y) * 128 + xc];
#pragma unroll
        for (int p = 0; p < 25; p++) e[p] = fmaf(wv, kb[k * 25 + p], e[p]);
    }
#pragma unroll
    for (int c = 0; c < 3; c++) {
        float acc = 0.f;
#pragma unroll
        for (int dy = 0; dy < 5; dy++) {
            int yy = y + dy - 2;
            yy = (yy < 0) ? -yy : ((yy > 127) ? 254 - yy : yy);
            const float* xr = &x[((b * 3 + c) * 128 + yy) * 128];
#pragma unroll
            for (int dx = 0; dx < 5; dx++) {
                int xx = xc + dx - 2;
                xx = (xx < 0) ? -xx : ((xx > 127) ? 254 - xx : xx);
                acc = fmaf(e[dy * 5 + dx], xr[xx], acc);
            }
        }
        out[((b * 3 + c) * 128 + y) * 128 + xc] = acc;
    }
}

// ---------------------------------------------------------------------------
extern "C" void kernel_launch(void* const* d_in, const int* in_sizes, int n_in,
                              void* d_out, int out_size)
{
    const float* x      = (const float*)d_in[0];
    const float* w_head = (const float*)d_in[1];
    const float* b_head = (const float*)d_in[2];
    const float* w_h1a  = (const float*)d_in[3];
    const float* b_h1a  = (const float*)d_in[4];
    const float* w_h1b  = (const float*)d_in[5];
    const float* b_h1b  = (const float*)d_in[6];
    const float* du1_w1 = (const float*)d_in[7];
    const float* du1_b1 = (const float*)d_in[8];
    const float* du1_w2 = (const float*)d_in[9];
    const float* du1_b2 = (const float*)d_in[10];
    const float* w_h2a  = (const float*)d_in[11];
    const float* b_h2a  = (const float*)d_in[12];
    const float* w_h2b  = (const float*)d_in[13];
    const float* b_h2b  = (const float*)d_in[14];
    const float* du2_w1 = (const float*)d_in[15];
    const float* du2_b1 = (const float*)d_in[16];
    const float* du2_w2 = (const float*)d_in[17];
    const float* du2_b2 = (const float*)d_in[18];
    const float* w_tail = (const float*)d_in[19];
    const float* b_tail = (const float*)d_in[20];
    const float* basis  = (const float*)d_in[21];

    unsigned *A, *Bb, *Wt, *Wts;
    float *mean, *scl;
    cudaGetSymbolAddress((void**)&A,    g_A);
    cudaGetSymbolAddress((void**)&Bb,   g_B);
    cudaGetSymbolAddress((void**)&mean, g_mean);
    cudaGetSymbolAddress((void**)&scl,  g_scl);
    cudaGetSymbolAddress((void**)&Wt,   g_Wt);
    cudaGetSymbolAddress((void**)&Wts,  g_Wts);

    cudaFuncSetAttribute(conv_mma_kernel,
                         cudaFuncAttributeMaxDynamicSharedMemorySize, CONV_SMEM);

    dim3 cgrid(128, B_);
    // 0: all repacks in one launch
    repack_all_kernel<<<dim3(576, 5), 128>>>(w_h1a, w_h1b, w_h2a, w_h2b, w_tail, Wt);
    // 1: head (fp32, Cin=3) -> q-ordered split planes in g_A
    conv3x3_head_kernel<<<dim3(64, 4, B_), 256>>>(x, w_head, b_head, A);
    // 2: conv h1a
    conv_mma_kernel<<<cgrid, 256, CONV_SMEM>>>(A,  Wt + 0 * WS, b_h1a, Bb, 128, 1, 1, 0, 0);
    // 3: conv h1b   <-- ncu captures this launch
    conv_mma_kernel<<<cgrid, 256, CONV_SMEM>>>(Bb, Wt + 1 * WS, b_h1b, A, 128, 1, 1, 0, 0);
    // SE 1 -> scaled weights for h2a
    se_pool_split_kernel<<<64, 256>>>(A, mean);
    se_fc_kernel<<<1, 1024>>>(mean, du1_w1, du1_b1, du1_w2, du1_b2, scl);
    scale_w_kernel<<<dim3(576, B_), 128>>>(Wt + 2 * WS, scl, Wts);
    // block 2
    conv_mma_kernel<<<cgrid, 256, CONV_SMEM>>>(A,  Wts, b_h2a, Bb, 128, 1, 1, 1, 0);
    conv_mma_kernel<<<cgrid, 256, CONV_SMEM>>>(Bb, Wt + 3 * WS, b_h2b, A, 128, 1, 1, 0, 0);
    // SE 2 -> scaled weights for tail
    se_pool_split_kernel<<<64, 256>>>(A, mean);
    se_fc_kernel<<<1, 1024>>>(mean, du2_w1, du2_b1, du2_w2, du2_b2, scl);
    scale_w_kernel<<<dim3(576, B_), 128>>>(Wt + 4 * WS, scl, Wts);
    // tail: split in, fp32 out (72 ch) -> g_B; balanced m-partition
    conv_mma_kernel<<<cgrid, 256, CONV_SMEM>>>(A, Wts, b_tail, Bb, 72, 0, 0, 1, 1);
    // dynamic filtering
    dynfilter_kernel<<<dim3(64, B_), 256>>>(x, (const float*)Bb, basis, (float*)d_out);
}

// round 15
// speedup vs baseline: 1.0334x; 1.0334x over previous
#include <cuda_runtime.h>
#include <cuda_bf16.h>
#include <math.h>
#include <cstdint>

// ===========================================================================
// DARM on GB300 (base sm_103 ISA): split-bf16 (3-term) mma.sync implicit-GEMM
// convs + fp32 head conv (split-output) + SE + per-pixel dynamic filtering.
// B=8, C=3, H=W=128, F=128, S=8, K=72.
// Activation layout (load-native): act[b][g][pl][y][x][q], q=0..7,
//   word q = packed(bf16 ci0 | bf16 ci1<<16), ci0=g*16+p, ci1=ci0+8,
//   p=(q>>1)+((q&1)<<2), pl = hi/lo split plane.
// R15: TAIL is a compile-time template param. TAIL=false -> constant
//   mb0/mtN=4, zero predicates in the hot loop (restores R11 codegen,
//   alu ~11%). TAIL=true -> balanced 3/2 m-partition for Cout=72.
// ===========================================================================

#define B_ 8
#define F_ 128
#define K_ 72
#define WS 147456         // words per repacked conv weight set (24 * 6144)

__device__ unsigned g_A[16777216];           // 64 MiB  (split act / ping)
__device__ unsigned g_B[16777216];           // 64 MiB  (split act / pong; fp32 tail out)
__device__ float    g_mean[B_ * F_];
__device__ float    g_scl[B_ * F_];
__device__ unsigned g_Wt[5 * WS];            // fragment-major repacked weights
__device__ unsigned g_Wts[B_ * WS];          // per-batch SE-scaled weights

// ---------------------------------------------------------------------------
// helpers
// ---------------------------------------------------------------------------
__device__ __forceinline__ uint32_t smem_u32(const void* p) {
    uint32_t a;
    asm("{ .reg .u64 t; cvta.to.shared.u64 t, %1; cvt.u32.u64 %0, t; }" : "=r"(a) : "l"(p));
    return a;
}
__device__ __forceinline__ void cpa16(uint32_t d, const void* s) {
    asm volatile("cp.async.cg.shared.global [%0], [%1], 16;" :: "r"(d), "l"(s) : "memory");
}
__device__ __forceinline__ void cpa16z(uint32_t d, const void* s, int sz) {
    asm volatile("cp.async.cg.shared.global [%0], [%1], 16, %2;" :: "r"(d), "l"(s), "r"(sz) : "memory");
}
#define CP_COMMIT() asm volatile("cp.async.commit_group;" ::: "memory")
#define CP_WAIT1()  asm volatile("cp.async.wait_group 1;" ::: "memory")

#define MMA_BF16(d, a, bb) \
    asm volatile("mma.sync.aligned.m16n8k16.row.col.f32.bf16.bf16.f32 " \
        "{%0,%1,%2,%3},{%4,%5,%6,%7},{%8,%9},{%0,%1,%2,%3};" \
        : "+f"((d)[0]), "+f"((d)[1]), "+f"((d)[2]), "+f"((d)[3]) \
        : "r"((a)[0]), "r"((a)[1]), "r"((a)[2]), "r"((a)[3]), "r"((bb)[0]), "r"((bb)[1]))

__device__ __forceinline__ uint32_t bfb(float v) {
    return (uint32_t)__bfloat16_as_ushort(__float2bfloat16(v));
}
__device__ __forceinline__ float bff(uint32_t b) { return __uint_as_float(b << 16); }
__device__ __forceinline__ void split2(float v, uint32_t& h, uint32_t& l) {
    h = bfb(v);
    l = bfb(v - bff(h));
}

// ---------------------------------------------------------------------------
// Weight repack (ALL 5 convs, fragment-major).
// grid (576, 5), block 128.
// ---------------------------------------------------------------------------
__global__ void repack_all_kernel(const float* __restrict__ w0, const float* __restrict__ w1,
                                  const float* __restrict__ w2, const float* __restrict__ w3,
                                  const float* __restrict__ w4, unsigned* __restrict__ wt)
{
    const float* w;
    int Cout = 128;
    switch (blockIdx.y) {
        case 0: w = w0; break;
        case 1: w = w1; break;
        case 2: w = w2; break;
        case 3: w = w3; break;
        default: w = w4; Cout = 72; break;
    }
    int idx = blockIdx.x * 128 + threadIdx.x;        // 0..73727
    int w_   = idx & 3;
    int lane = (idx >> 2) & 31;
    int mblk = (idx >> 7) & 7;
    int rest = idx >> 10;                            // t*3 + kx
    int kx = rest % 3;
    int t  = rest / 3;
    int cg = t / 3, ky = t - cg * 3;
    int p  = (lane & 3) + ((w_ >> 1) << 2);
    int co = mblk * 16 + (lane >> 2) + ((w_ & 1) << 3);
    int ci0 = cg * 16 + p, ci1 = ci0 + 8;
    float v0 = 0.f, v1 = 0.f;
    if (co < Cout) {
        v0 = w[co * 1152 + ci0 * 9 + ky * 3 + kx];
        v1 = w[co * 1152 + ci1 * 9 + ky * 3 + kx];
    }
    uint32_t h0, l0, h1, l1;
    split2(v0, h0, l0); split2(v1, h1, l1);
    unsigned* o = wt + (size_t)blockIdx.y * WS + t * 6144;
    int base = (kx * 8 + mblk) * 128 + lane * 4 + w_;
    o[base]        = h0 | (h1 << 16);
    o[base + 3072] = l0 | (l1 << 16);
}

// ---------------------------------------------------------------------------
// SE weight-scale (fragment-major indexing).
// grid (576, 8), block 128.
// ---------------------------------------------------------------------------
__global__ void scale_w_kernel(const unsigned* __restrict__ wt, const float* __restrict__ scl,
                               unsigned* __restrict__ wts)
{
    int b = blockIdx.y;
    int idx = blockIdx.x * 128 + threadIdx.x;
    int w_   = idx & 3;
    int lane = (idx >> 2) & 31;
    int mblk = (idx >> 7) & 7;
    int rest = idx >> 10;
    int kx = rest % 3;
    int t  = rest / 3;
    int cg = t / 3;
    int p  = (lane & 3) + ((w_ >> 1) << 2);
    int ci0 = cg * 16 + p, ci1 = ci0 + 8;
    int base = t * 6144 + (kx * 8 + mblk) * 128 + lane * 4 + w_;
    unsigned wh = wt[base], wl = wt[base + 3072];
    float s0 = scl[b * 128 + ci0];
    float s1 = scl[b * 128 + ci1];
    float v0 = (bff(wh & 0xffffu) + bff(wl & 0xffffu)) * s0;
    float v1 = (bff(wh >> 16) + bff(wl >> 16)) * s1;
    uint32_t h0, l0, h1, l1;
    split2(v0, h0, l0); split2(v1, h1, l1);
    unsigned* o = wts + (size_t)b * WS;
    o[base]        = h0 | (h1 << 16);
    o[base + 3072] = l0 | (l1 << 16);
}

// ---------------------------------------------------------------------------
// split-bf16 mma conv, Cin=128. CTA: M=128 co x N=128 px (2 rows x 64 cols).
// 8 warps (2m x 4n), warp tile 64x32 -> mt<=4, nf=4 m16n8k16 frags.
// K = 1152: 24 chunks (cg,ky) x 3 kx x 16 ci. 3 MMAs (hi*hi,hi*lo,lo*hi).
// TAIL (compile-time): false -> mb0=hi*4, mtN=4 (zero predicates);
//   true (Cout=72) -> lower warps mblks 0..2, upper mblks 3..4 (balanced).
// smem b32: A bufs 3 x 6144 (fragment-major)          @ 0
//           B bufs 2 x 4224 ([pl][rs4][xs66][q8])     @ 18432
// Pipeline: 2-chunk slack, wait_group 1, one commit per iteration.
// grid (128 = 64 rowpairs x 2 colhalves, 8 batch), block 256, 2 CTAs/SM.
// ---------------------------------------------------------------------------
#define CONV_SMEM ((3 * 6144 + 2 * 4224) * 4)   // 107520 B

template <bool TAIL>
__global__ __launch_bounds__(256, 2)
void conv_mma_kernel(const unsigned* __restrict__ actin, const unsigned* __restrict__ wt,
                     const float* __restrict__ bias, void* __restrict__ outp,
                     int Cout, int doRelu, int splitOut, int perBatchW)
{
    extern __shared__ unsigned sm32[];
    const uint32_t sb = smem_u32(sm32);

    const int tid  = threadIdx.x;
    const int wid  = tid >> 5;                  // 0..7
    const int lane = tid & 31;
    const int tid4 = lane & 3;
    const int grp  = lane >> 2;
    const int hi   = wid >> 2;                  // 0 = lower-m, 1 = upper-m
    const int n0 = (wid & 3) * 32;              // 0..96
    const int lane4 = lane * 4;
    // m-partition: normal = {0..3 | 4..7}; tail = {0..2 | 3..4}
    const int mb0 = TAIL ? (hi ? 3 : 0) : hi * 4;
    const int mtN = TAIL ? (hi ? 2 : 3) : 4;
    const int m0  = mb0 * 16;
    const int b  = blockIdx.y;
    const int rp = blockIdx.x >> 1;             // row-pair 0..63
    const int ch = blockIdx.x & 1;              // col-half
    const int y0 = rp * 2;
    const int x0 = ch * 64;

    const unsigned* wtb = wt + (perBatchW ? (size_t)b * WS : 0);

    // per-thread B fragment bases: off = r*528 + xloc*8 + tid4*2 (+ky*528 +kx*8)
    int nbase[4];
#pragma unroll
    for (int nf = 0; nf < 4; nf++) {
        int n = n0 + nf * 8 + grp;
        nbase[nf] = (n >> 6) * 528 + (n & 63) * 8 + tid4 * 2;
    }

    float d[4][4][4];
#pragma unroll
    for (int mt = 0; mt < 4; mt++)
#pragma unroll
        for (int nf = 0; nf < 4; nf++)
#pragma unroll
            for (int i = 0; i < 4; i++) d[mt][nf][i] = 0.f;

    auto loadA = [&](int t, int buf) {
        const unsigned* src = wtb + t * 6144;
        const uint32_t dst = sb + (uint32_t)buf * 24576u;
#pragma unroll
        for (int i = tid; i < 1536; i += 256)
            cpa16(dst + (uint32_t)i * 16u, src + i * 4);
    };
    // B: 1056 contiguous cpa16. i = ((pl*4+rs)*66+xs)*2+qh
    auto loadB = [&](int cg, int buf) {
        const uint32_t dst = sb + 73728u + (buf ? 16896u : 0u);
        const unsigned* basep = actin + ((size_t)b * 8 + cg) * 262144;
        for (int i = tid; i < 1056; i += 256) {
            int qh = i & 1, r = i >> 1;          // r = (pl*4+rs)*66 + xs
            int xs = r % 66;
            int r2 = r / 66;                     // pl*4 + rs
            int rs = r2 & 3, pl = r2 >> 2;
            int y = y0 - 1 + rs, xi = x0 - 1 + xs;
            bool ok = ((unsigned)y < 128u) && ((unsigned)xi < 128u);
            const unsigned* src = basep + pl * 131072
                                + (ok ? ((y * 128 + xi) * 8) : 0) + qh * 4;
            uint32_t doff = (uint32_t)(pl * 2112 + rs * 528 + xs * 8 + qh * 4) * 4u;
            cpa16z(dst + doff, src, ok ? 16 : 0);
        }
    };

    // prologue: G0 = {A0, B0}, G1 = {A1}
    loadB(0, 0);
    loadA(0, 0);
    CP_COMMIT();
    loadA(1, 1);
    CP_COMMIT();

    for (int t = 0; t < 24; ++t) {
        const int cg = t / 3;
        const int ky = t - cg * 3;
        CP_WAIT1();                      // G_t complete (G_{t+1} may be in flight)
        __syncthreads();
        const int tn = t + 2;
        if (tn < 24) {
            loadA(tn, tn % 3);
            if (tn % 3 == 0) loadB(tn / 3, (tn / 3) & 1);
        }
        CP_COMMIT();                     // one group per iteration (may be empty)

        const unsigned* As = sm32 + (t % 3) * 6144;
        const unsigned* Bs = sm32 + 18432 + (cg & 1) * 4224;
        const int kyo = ky * 528;

#pragma unroll
        for (int kx = 0; kx < 3; ++kx) {
            uint32_t ah[4][4], al[4][4];
#pragma unroll
            for (int mt = 0; mt < 4; mt++) {
                if (!TAIL || mt < mtN) {
                    int ab = (kx * 8 + mb0 + mt) * 128 + lane4;
                    *(uint4*)ah[mt] = *(const uint4*)(As + ab);
                    *(uint4*)al[mt] = *(const uint4*)(As + ab + 3072);
                }
            }
            uint32_t bh[4][2], bl[4][2];
#pragma unroll
            for (int nf = 0; nf < 4; nf++) {
                int off = nbase[nf] + kyo + kx * 8;
                *(uint2*)bh[nf] = *(const uint2*)(Bs + off);
                *(uint2*)bl[nf] = *(const uint2*)(Bs + off + 2112);
            }
#pragma unroll
            for (int nf = 0; nf < 4; nf++)
#pragma unroll
                for (int mt = 0; mt < 4; mt++)
                    if (!TAIL || mt < mtN) MMA_BF16(d[mt][nf], ah[mt], bh[nf]);
#pragma unroll
            for (int nf = 0; nf < 4; nf++)
#pragma unroll
                for (int mt = 0; mt < 4; mt++)
                    if (!TAIL || mt < mtN) MMA_BF16(d[mt][nf], ah[mt], bl[nf]);
#pragma unroll
            for (int nf = 0; nf < 4; nf++)
#pragma unroll
                for (int mt = 0; mt < 4; mt++)
                    if (!TAIL || mt < mtN) MMA_BF16(d[mt][nf], al[mt], bh[nf]);
        }
    }

    // ---- epilogue ----
    if (splitOut) {
        unsigned* outu = (unsigned*)outp;
#pragma unroll
        for (int mt = 0; mt < 4; mt++) {
            if (TAIL && mt >= mtN) continue;
            const int co0 = m0 + mt * 16 + grp;       // p = grp (0..7)
            const int g = co0 >> 4;
            const int q = 2 * (grp & 3) + (grp >> 2);
            const float bv0 = bias[co0], bv1 = bias[co0 + 8];
            const size_t bhi = (((size_t)b * 8 + g) * 2 + 0) * 131072;
            const size_t blo = bhi + 131072;
#pragma unroll
            for (int nf = 0; nf < 4; nf++) {
                const int n = n0 + nf * 8 + 2 * tid4;
                const int pix = (y0 + (n >> 6)) * 128 + x0 + (n & 63);
                float v0 = d[mt][nf][0] + bv0, v1 = d[mt][nf][1] + bv0;
                float v2 = d[mt][nf][2] + bv1, v3 = d[mt][nf][3] + bv1;
                if (doRelu) {
                    v0 = fmaxf(v0, 0.f); v1 = fmaxf(v1, 0.f);
                    v2 = fmaxf(v2, 0.f); v3 = fmaxf(v3, 0.f);
                }
                uint32_t h0, l0, h1, l1, h2, l2, h3, l3;
                split2(v0, h0, l0); split2(v1, h1, l1);
                split2(v2, h2, l2); split2(v3, h3, l3);
                outu[bhi + (size_t)pix * 8 + q]       = h0 | (h2 << 16);
                outu[bhi + (size_t)(pix + 1) * 8 + q] = h1 | (h3 << 16);
                outu[blo + (size_t)pix * 8 + q]       = l0 | (l2 << 16);
                outu[blo + (size_t)(pix + 1) * 8 + q] = l1 | (l3 << 16);
            }
        }
    } else {
        float* outf = (float*)outp;
#pragma unroll
        for (int mt = 0; mt < 4; mt++) {
            if (TAIL && mt >= mtN) continue;
            const int co0 = m0 + mt * 16 + grp;
            const int co1 = co0 + 8;
            const float bv0 = (co0 < Cout) ? bias[co0] : 0.f;
            const float bv1 = (co1 < Cout) ? bias[co1] : 0.f;
#pragma unroll
            for (int nf = 0; nf < 4; nf++) {
                const int n = n0 + nf * 8 + 2 * tid4;
                const int y = y0 + (n >> 6), x = x0 + (n & 63);
                if (co0 < Cout) {
                    float v0 = d[mt][nf][0] + bv0, v1 = d[mt][nf][1] + bv0;
                    if (doRelu) { v0 = fmaxf(v0, 0.f); v1 = fmaxf(v1, 0.f); }
                    *(float2*)(outf + (((size_t)b * Cout + co0) * 128 + y) * 128 + x)
                        = make_float2(v0, v1);
                }
                if (co1 < Cout) {
                    float v2 = d[mt][nf][2] + bv1, v3 = d[mt][nf][3] + bv1;
                    if (doRelu) { v2 = fmaxf(v2, 0.f); v3 = fmaxf(v3, 0.f); }
                    *(float2*)(outf + (((size_t)b * Cout + co1) * 128 + y) * 128 + x)
                        = make_float2(v2, v3);
                }
            }
        }
    }
}

// ---------------------------------------------------------------------------
// fp32 head conv (Cin=3, Cout=128), writes the q-ordered SPLIT layout.
// ---------------------------------------------------------------------------
__global__ __launch_bounds__(256, 2)
void conv3x3_head_kernel(const float* __restrict__ in, const float* __restrict__ w,
                         const float* __restrict__ bias, unsigned* __restrict__ out)
{
    const int Cin = 3;
    __shared__ float s_in[3 * 18 * 18];
    __shared__ float s_w[32 * 3 * 9];
    const int tid = threadIdx.x;
    const int b   = blockIdx.z;
    const int coG = blockIdx.y;
    const int ty  = blockIdx.x >> 3;
    const int tx  = blockIdx.x & 7;
    const int y0 = ty * 16, x0 = tx * 16;
    const int co_base = tid >> 5;              // 0..7 = p
    const int pid = tid & 31;
    const int y  = pid >> 1;
    const int xb = (pid & 1) * 8;

    float acc[4][8];
#pragma unroll
    for (int j = 0; j < 4; j++)
#pragma unroll
        for (int p = 0; p < 8; p++) acc[j][p] = 0.f;

    for (int idx = tid; idx < 3 * 324; idx += 256) {
        int ci = idx / 324;
        int r  = idx - ci * 324;
        int iy = r / 18, ix = r - iy * 18;
        int gy = y0 - 1 + iy, gx = x0 - 1 + ix;
        float v = 0.f;
        if ((unsigned)gy < 128u && (unsigned)gx < 128u)
            v = in[((b * Cin + ci) * 128 + gy) * 128 + gx];
        s_in[idx] = v;
    }
    for (int idx = tid; idx < 32 * 27; idx += 256) {
        int l = idx / 27;
        int r = idx - l * 27;
        s_w[idx] = w[(coG * 32 + l) * 27 + r];
    }
    __syncthreads();

#pragma unroll
    for (int ci = 0; ci < 3; ci++) {
#pragma unroll
        for (int ky = 0; ky < 3; ky++) {
            float r[10];
            const float* row = &s_in[ci * 324 + (y + ky) * 18 + xb];
#pragma unroll
            for (int i = 0; i < 10; i++) r[i] = row[i];
#pragma unroll
            for (int kx = 0; kx < 3; kx++) {
#pragma unroll
                for (int j = 0; j < 4; j++) {
                    float wv = s_w[(co_base + j * 8) * 27 + ci * 9 + ky * 3 + kx];
#pragma unroll
                    for (int p = 0; p < 8; p++)
                        acc[j][p] = fmaf(wv, r[p + kx], acc[j][p]);
                }
            }
        }
    }

    float bv[4];
#pragma unroll
    for (int j = 0; j < 4; j++) bv[j] = bias[coG * 32 + co_base + j * 8];

    const int q = 2 * (co_base & 3) + (co_base >> 2);
    const int g0 = 2 * coG, g1 = 2 * coG + 1;
    const size_t b0h = (((size_t)b * 8 + g0) * 2 + 0) * 131072;
    const size_t b1h = (((size_t)b * 8 + g1) * 2 + 0) * 131072;
#pragma unroll
    for (int p = 0; p < 8; p++) {
        size_t pix8 = (size_t)((y0 + y) * 128 + x0 + xb + p) * 8 + q;
        uint32_t h0, q0, h1, q1, h2, q2, h3, q3;
        split2(acc[0][p] + bv[0], h0, q0);
        split2(acc[1][p] + bv[1], h1, q1);
        split2(acc[2][p] + bv[2], h2, q2);
        split2(acc[3][p] + bv[3], h3, q3);
        out[b0h + pix8]          = h0 | (h1 << 16);
        out[b0h + 131072 + pix8] = q0 | (q1 << 16);
        out[b1h + pix8]          = h2 | (h3 << 16);
        out[b1h + 131072 + pix8] = q2 | (q3 << 16);
    }
}

// ---------------------------------------------------------------------------
// SE pool on q-ordered split activations. One block per (b,g).
// grid 64, block 256.
// ---------------------------------------------------------------------------
__global__ void se_pool_split_kernel(const unsigned* __restrict__ act, float* __restrict__ mean)
{
    const int bg = blockIdx.x;                 // b*8 + g
    const int b = bg >> 3, g = bg & 7;
    const uint4* basep = (const uint4*)(act + (size_t)bg * 262144);
    const int t = threadIdx.x;

    float s[8];
#pragma unroll
    for (int j = 0; j < 8; j++) s[j] = 0.f;

    for (int k = 0; k < 256; k++) {
        uint4 v = basep[t + k * 256];
        s[0] += bff(v.x & 0xffffu); s[1] += bff(v.x >> 16);
        s[2] += bff(v.y & 0xffffu); s[3] += bff(v.y >> 16);
        s[4] += bff(v.z & 0xffffu); s[5] += bff(v.z >> 16);
        s[6] += bff(v.w & 0xffffu); s[7] += bff(v.w >> 16);
    }
#pragma unroll
    for (int o = 16; o >= 2; o >>= 1)
#pragma unroll
        for (int j = 0; j < 8; j++) s[j] += __shfl_xor_sync(0xffffffffu, s[j], o);

    __shared__ float cs[16];
    if (t < 16) cs[t] = 0.f;
    __syncthreads();
    int lane = t & 31;
    if (lane < 2) {
#pragma unroll
        for (int j = 0; j < 8; j++) atomicAdd(&cs[lane * 8 + j], s[j]);
    }
    __syncthreads();
    if (t < 16) {
        int qh = t >> 3, jh = t & 7;
        int j = jh >> 1, half = jh & 1;
        int q = qh * 4 + j;
        int p = (q >> 1) + ((q & 1) << 2);
        int c = g * 16 + p + half * 8;
        mean[b * 128 + c] = cs[t] * (1.f / 16384.f);
    }
}

__global__ void se_fc_kernel(const float* __restrict__ mean,
                             const float* __restrict__ w1, const float* __restrict__ b1,
                             const float* __restrict__ w2, const float* __restrict__ b2,
                             float* __restrict__ scl)
{
    __shared__ float smn[8][128];
    __shared__ float s1[8][8];
    int t = threadIdx.x;
    smn[t >> 7][t & 127] = mean[t];
    __syncthreads();
    if (t < 64) {
        int bb = t >> 3, j = t & 7;
        float a = b1[j];
#pragma unroll 4
        for (int c = 0; c < 128; c++) a = fmaf(w1[j * 128 + c], smn[bb][c], a);
        s1[bb][j] = fmaxf(a, 0.f);
    }
    __syncthreads();
    int bb = t >> 7, co = t & 127;
    float a = b2[co];
#pragma unroll
    for (int j = 0; j < 8; j++) a = fmaf(w2[co * 8 + j], s1[bb][j], a);
    scl[t] = 1.f / (1.f + expf(-a));
}

// ---------------------------------------------------------------------------
// Dynamic filtering (unchanged)
// ---------------------------------------------------------------------------
__global__ __launch_bounds__(256)
void dynfilter_kernel(const float* __restrict__ x, const float* __restrict__ wgt,
                      const float* __restrict__ basis, float* __restrict__ out)
{
    __shared__ float kb[K_ * 25];
    for (int i = threadIdx.x; i < K_ * 25; i += 256) kb[i] = basis[i];
    __syncthreads();
    int b = blockIdx.y;
    int y = blockIdx.x * 2 + (threadIdx.x >> 7);
    int xc = threadIdx.x & 127;
    float e[25];
#pragma unroll
    for (int p = 0; p < 25; p++) e[p] = 0.f;
    for (int k = 0; k < K_; k++) {
        float wv = wgt[((b * K_ + k) * 128 + y) * 128 + xc];
#pragma unroll
        for (int p = 0; p < 25; p++) e[p] = fmaf(wv, kb[k * 25 + p], e[p]);
    }
#pragma unroll
    for (int c = 0; c < 3; c++) {
        float acc = 0.f;
#pragma unroll
        for (int dy = 0; dy < 5; dy++) {
            int yy = y + dy - 2;
            yy = (yy < 0) ? -yy : ((yy > 127) ? 254 - yy : yy);
            const float* xr = &x[((b * 3 + c) * 128 + yy) * 128];
#pragma unroll
            for (int dx = 0; dx < 5; dx++) {
                int xx = xc + dx - 2;
                xx = (xx < 0) ? -xx : ((xx > 127) ? 254 - xx : xx);
                acc = fmaf(e[dy * 5 + dx], xr[xx], acc);
            }
        }
        out[((b * 3 + c) * 128 + y) * 128 + xc] = acc;
    }
}

// ---------------------------------------------------------------------------
extern "C" void kernel_launch(void* const* d_in, const int* in_sizes, int n_in,
                              void* d_out, int out_size)
{
    const float* x      = (const float*)d_in[0];
    const float* w_head = (const float*)d_in[1];
    const float* b_head = (const float*)d_in[2];
    const float* w_h1a  = (const float*)d_in[3];
    const float* b_h1a  = (const float*)d_in[4];
    const float* w_h1b  = (const float*)d_in[5];
    const float* b_h1b  = (const float*)d_in[6];
    const float* du1_w1 = (const float*)d_in[7];
    const float* du1_b1 = (const float*)d_in[8];
    const float* du1_w2 = (const float*)d_in[9];
    const float* du1_b2 = (const float*)d_in[10];
    const float* w_h2a  = (const float*)d_in[11];
    const float* b_h2a  = (const float*)d_in[12];
    const float* w_h2b  = (const float*)d_in[13];
    const float* b_h2b  = (const float*)d_in[14];
    const float* du2_w1 = (const float*)d_in[15];
    const float* du2_b1 = (const float*)d_in[16];
    const float* du2_w2 = (const float*)d_in[17];
    const float* du2_b2 = (const float*)d_in[18];
    const float* w_tail = (const float*)d_in[19];
    const float* b_tail = (const float*)d_in[20];
    const float* basis  = (const float*)d_in[21];

    unsigned *A, *Bb, *Wt, *Wts;
    float *mean, *scl;
    cudaGetSymbolAddress((void**)&A,    g_A);
    cudaGetSymbolAddress((void**)&Bb,   g_B);
    cudaGetSymbolAddress((void**)&mean, g_mean);
    cudaGetSymbolAddress((void**)&scl,  g_scl);
    cudaGetSymbolAddress((void**)&Wt,   g_Wt);
    cudaGetSymbolAddress((void**)&Wts,  g_Wts);

    cudaFuncSetAttribute(conv_mma_kernel<false>,
                         cudaFuncAttributeMaxDynamicSharedMemorySize, CONV_SMEM);
    cudaFuncSetAttribute(conv_mma_kernel<true>,
                         cudaFuncAttributeMaxDynamicSharedMemorySize, CONV_SMEM);

    dim3 cgrid(128, B_);
    // 0: all repacks in one launch
    repack_all_kernel<<<dim3(576, 5), 128>>>(w_h1a, w_h1b, w_h2a, w_h2b, w_tail, Wt);
    // 1: head (fp32, Cin=3) -> q-ordered split planes in g_A
    conv3x3_head_kernel<<<dim3(64, 4, B_), 256>>>(x, w_head, b_head, A);
    // 2: conv h1a
    conv_mma_kernel<false><<<cgrid, 256, CONV_SMEM>>>(A,  Wt + 0 * WS, b_h1a, Bb, 128, 1, 1, 0);
    // 3: conv h1b   <-- ncu captures this launch
    conv_mma_kernel<false><<<cgrid, 256, CONV_SMEM>>>(Bb, Wt + 1 * WS, b_h1b, A, 128, 1, 1, 0);
    // SE 1 -> scaled weights for h2a
    se_pool_split_kernel<<<64, 256>>>(A, mean);
    se_fc_kernel<<<1, 1024>>>(mean, du1_w1, du1_b1, du1_w2, du1_b2, scl);
    scale_w_kernel<<<dim3(576, B_), 128>>>(Wt + 2 * WS, scl, Wts);
    // block 2
    conv_mma_kernel<false><<<cgrid, 256, CONV_SMEM>>>(A,  Wts, b_h2a, Bb, 128, 1, 1, 1);
    conv_mma_kernel<false><<<cgrid, 256, CONV_SMEM>>>(Bb, Wt + 3 * WS, b_h2b, A, 128, 1, 1, 0);
    // SE 2 -> scaled weights for tail
    se_pool_split_kernel<<<64, 256>>>(A, mean);
    se_fc_kernel<<<1, 1024>>>(mean, du2_w1, du2_b1, du2_w2, du2_b2, scl);
    scale_w_kernel<<<dim3(576, B_), 128>>>(Wt + 4 * WS, scl, Wts);
    // tail: split in, fp32 out (72 ch) -> g_B; balanced m-partition (TAIL)
    conv_mma_kernel<true><<<cgrid, 256, CONV_SMEM>>>(A, Wts, b_tail, Bb, 72, 0, 0, 1);
    // dynamic filtering
    dynfilter_kernel<<<dim3(64, B_), 256>>>(x, (const float*)Bb, basis, (float*)d_out);
}

// round 16
// speedup vs baseline: 1.1238x; 1.0875x over previous
#include <cuda_runtime.h>
#include <cuda_bf16.h>
#include <math.h>
#include <cstdint>

// ===========================================================================
// DARM on GB300 (base sm_103 ISA): split-bf16 (3-term) mma.sync implicit-GEMM
// convs + fp32 head conv (split-output) + SE + per-pixel dynamic filtering.
// B=8, C=3, H=W=128, F=128, S=8, K=72.
// Activation layout (load-native): act[b][g][pl][y][x][q], q=0..7,
//   word q = packed(bf16 ci0 | bf16 ci1<<16), ci0=g*16+p, ci1=ci0+8,
//   p=(q>>1)+((q&1)<<2), pl = hi/lo split plane.
// R16: epilogue fusions.
//   - SE pooling fused into h1b/h2b conv epilogues (shfl + smem + atomicAdd);
//     se_pool kernels deleted; se_fc applies 1/16384.
//   - dynamic filtering fused into the tail conv (wgt -> smem -> e[25] ->
//     output); dynfilter kernel + 75MB wgt traffic deleted.
// ===========================================================================

#define B_ 8
#define F_ 128
#define K_ 72
#define WS 147456         // words per repacked conv weight set (24 * 6144)

__device__ unsigned g_A[16777216];           // 64 MiB  (split act / ping)
__device__ unsigned g_B[16777216];           // 64 MiB  (split act / pong)
__device__ float    g_mean1[B_ * F_];
__device__ float    g_mean2[B_ * F_];
__device__ float    g_scl[B_ * F_];
__device__ unsigned g_Wt[5 * WS];            // fragment-major repacked weights
__device__ unsigned g_Wts[B_ * WS];          // per-batch SE-scaled weights

// ---------------------------------------------------------------------------
// helpers
// ---------------------------------------------------------------------------
__device__ __forceinline__ uint32_t smem_u32(const void* p) {
    uint32_t a;
    asm("{ .reg .u64 t; cvta.to.shared.u64 t, %1; cvt.u32.u64 %0, t; }" : "=r"(a) : "l"(p));
    return a;
}
__device__ __forceinline__ void cpa16(uint32_t d, const void* s) {
    asm volatile("cp.async.cg.shared.global [%0], [%1], 16;" :: "r"(d), "l"(s) : "memory");
}
__device__ __forceinline__ void cpa16z(uint32_t d, const void* s, int sz) {
    asm volatile("cp.async.cg.shared.global [%0], [%1], 16, %2;" :: "r"(d), "l"(s), "r"(sz) : "memory");
}
#define CP_COMMIT() asm volatile("cp.async.commit_group;" ::: "memory")
#define CP_WAIT1()  asm volatile("cp.async.wait_group 1;" ::: "memory")

#define MMA_BF16(d, a, bb) \
    asm volatile("mma.sync.aligned.m16n8k16.row.col.f32.bf16.bf16.f32 " \
        "{%0,%1,%2,%3},{%4,%5,%6,%7},{%8,%9},{%0,%1,%2,%3};" \
        : "+f"((d)[0]), "+f"((d)[1]), "+f"((d)[2]), "+f"((d)[3]) \
        : "r"((a)[0]), "r"((a)[1]), "r"((a)[2]), "r"((a)[3]), "r"((bb)[0]), "r"((bb)[1]))

__device__ __forceinline__ uint32_t bfb(float v) {
    return (uint32_t)__bfloat16_as_ushort(__float2bfloat16(v));
}
__device__ __forceinline__ float bff(uint32_t b) { return __uint_as_float(b << 16); }
__device__ __forceinline__ void split2(float v, uint32_t& h, uint32_t& l) {
    h = bfb(v);
    l = bfb(v - bff(h));
}

// ---------------------------------------------------------------------------
// Weight repack (ALL 5 convs, fragment-major) + zero the SE mean buffers.
// grid (576, 5), block 128.
// ---------------------------------------------------------------------------
__global__ void repack_all_kernel(const float* __restrict__ w0, const float* __restrict__ w1,
                                  const float* __restrict__ w2, const float* __restrict__ w3,
                                  const float* __restrict__ w4, unsigned* __restrict__ wt,
                                  float* __restrict__ mean1, float* __restrict__ mean2)
{
    if (blockIdx.y == 0 && blockIdx.x < 8) {
        int i = blockIdx.x * 128 + threadIdx.x;
        mean1[i] = 0.f;
        mean2[i] = 0.f;
    }
    const float* w;
    int Cout = 128;
    switch (blockIdx.y) {
        case 0: w = w0; break;
        case 1: w = w1; break;
        case 2: w = w2; break;
        case 3: w = w3; break;
        default: w = w4; Cout = 72; break;
    }
    int idx = blockIdx.x * 128 + threadIdx.x;        // 0..73727
    int w_   = idx & 3;
    int lane = (idx >> 2) & 31;
    int mblk = (idx >> 7) & 7;
    int rest = idx >> 10;                            // t*3 + kx
    int kx = rest % 3;
    int t  = rest / 3;
    int cg = t / 3, ky = t - cg * 3;
    int p  = (lane & 3) + ((w_ >> 1) << 2);
    int co = mblk * 16 + (lane >> 2) + ((w_ & 1) << 3);
    int ci0 = cg * 16 + p, ci1 = ci0 + 8;
    float v0 = 0.f, v1 = 0.f;
    if (co < Cout) {
        v0 = w[co * 1152 + ci0 * 9 + ky * 3 + kx];
        v1 = w[co * 1152 + ci1 * 9 + ky * 3 + kx];
    }
    uint32_t h0, l0, h1, l1;
    split2(v0, h0, l0); split2(v1, h1, l1);
    unsigned* o = wt + (size_t)blockIdx.y * WS + t * 6144;
    int base = (kx * 8 + mblk) * 128 + lane * 4 + w_;
    o[base]        = h0 | (h1 << 16);
    o[base + 3072] = l0 | (l1 << 16);
}

// ---------------------------------------------------------------------------
// SE weight-scale (fragment-major indexing).
// grid (576, 8), block 128.
// ---------------------------------------------------------------------------
__global__ void scale_w_kernel(const unsigned* __restrict__ wt, const float* __restrict__ scl,
                               unsigned* __restrict__ wts)
{
    int b = blockIdx.y;
    int idx = blockIdx.x * 128 + threadIdx.x;
    int w_   = idx & 3;
    int lane = (idx >> 2) & 31;
    int mblk = (idx >> 7) & 7;
    int rest = idx >> 10;
    int kx = rest % 3;
    int t  = rest / 3;
    int cg = t / 3;
    int p  = (lane & 3) + ((w_ >> 1) << 2);
    int ci0 = cg * 16 + p, ci1 = ci0 + 8;
    int base = t * 6144 + (kx * 8 + mblk) * 128 + lane * 4 + w_;
    unsigned wh = wt[base], wl = wt[base + 3072];
    float s0 = scl[b * 128 + ci0];
    float s1 = scl[b * 128 + ci1];
    float v0 = (bff(wh & 0xffffu) + bff(wl & 0xffffu)) * s0;
    float v1 = (bff(wh >> 16) + bff(wl >> 16)) * s1;
    uint32_t h0, l0, h1, l1;
    split2(v0, h0, l0); split2(v1, h1, l1);
    unsigned* o = wts + (size_t)b * WS;
    o[base]        = h0 | (h1 << 16);
    o[base + 3072] = l0 | (l1 << 16);
}

// ---------------------------------------------------------------------------
// split-bf16 mma conv, Cin=128. CTA: M=128 co x N=128 px (2 rows x 64 cols).
// 8 warps (2m x 4n), warp tile 64x32 -> mt<=4, nf=4 m16n8k16 frags.
// K = 1152: 24 chunks (cg,ky) x 3 kx x 16 ci. 3 MMAs (hi*hi,hi*lo,lo*hi).
// TAIL=false: mb0=hi*4, mtN=4 (zero predicates); splitOut epilogue with
//   optional fused SE pooling (seMean != nullptr).
// TAIL=true (Cout=72): balanced m-partition {0..2 | 3..4}; fused dynamic
//   filtering epilogue: wgt -> smem, e[25] per pixel, 3-ch reflect output.
// smem b32: A bufs 3 x 6144 @ 0, B bufs 2 x 4224 @ 18432.
// Pipeline: 2-chunk slack, wait_group 1, one commit per iteration.
// grid (128, 8), block 256, 2 CTAs/SM.
// ---------------------------------------------------------------------------
#define CONV_SMEM ((3 * 6144 + 2 * 4224) * 4)   // 107520 B

template <bool TAIL>
__global__ __launch_bounds__(256, 2)
void conv_mma_kernel(const unsigned* __restrict__ actin, const unsigned* __restrict__ wt,
                     const float* __restrict__ bias, void* __restrict__ outp,
                     int Cout, int doRelu, int perBatchW,
                     float* __restrict__ seMean,
                     const float* __restrict__ xin, const float* __restrict__ basis,
                     float* __restrict__ outF)
{
    extern __shared__ unsigned sm32[];
    const uint32_t sb = smem_u32(sm32);

    const int tid  = threadIdx.x;
    const int wid  = tid >> 5;                  // 0..7
    const int lane = tid & 31;
    const int tid4 = lane & 3;
    const int grp  = lane >> 2;
    const int hi   = wid >> 2;                  // 0 = lower-m, 1 = upper-m
    const int n0 = (wid & 3) * 32;              // 0..96
    const int lane4 = lane * 4;
    const int mb0 = TAIL ? (hi ? 3 : 0) : hi * 4;
    const int mtN = TAIL ? (hi ? 2 : 3) : 4;
    const int m0  = mb0 * 16;
    const int b  = blockIdx.y;
    const int rp = blockIdx.x >> 1;             // row-pair 0..63
    const int ch = blockIdx.x & 1;              // col-half
    const int y0 = rp * 2;
    const int x0 = ch * 64;

    const unsigned* wtb = wt + (perBatchW ? (size_t)b * WS : 0);

    int nbase[4];
#pragma unroll
    for (int nf = 0; nf < 4; nf++) {
        int n = n0 + nf * 8 + grp;
        nbase[nf] = (n >> 6) * 528 + (n & 63) * 8 + tid4 * 2;
    }

    float d[4][4][4];
#pragma unroll
    for (int mt = 0; mt < 4; mt++)
#pragma unroll
        for (int nf = 0; nf < 4; nf++)
#pragma unroll
            for (int i = 0; i < 4; i++) d[mt][nf][i] = 0.f;

    auto loadA = [&](int t, int buf) {
        const unsigned* src = wtb + t * 6144;
        const uint32_t dst = sb + (uint32_t)buf * 24576u;
#pragma unroll
        for (int i = tid; i < 1536; i += 256)
            cpa16(dst + (uint32_t)i * 16u, src + i * 4);
    };
    auto loadB = [&](int cg, int buf) {
        const uint32_t dst = sb + 73728u + (buf ? 16896u : 0u);
        const unsigned* basep = actin + ((size_t)b * 8 + cg) * 262144;
        for (int i = tid; i < 1056; i += 256) {
            int qh = i & 1, r = i >> 1;          // r = (pl*4+rs)*66 + xs
            int xs = r % 66;
            int r2 = r / 66;                     // pl*4 + rs
            int rs = r2 & 3, pl = r2 >> 2;
            int y = y0 - 1 + rs, xi = x0 - 1 + xs;
            bool ok = ((unsigned)y < 128u) && ((unsigned)xi < 128u);
            const unsigned* src = basep + pl * 131072
                                + (ok ? ((y * 128 + xi) * 8) : 0) + qh * 4;
            uint32_t doff = (uint32_t)(pl * 2112 + rs * 528 + xs * 8 + qh * 4) * 4u;
            cpa16z(dst + doff, src, ok ? 16 : 0);
        }
    };

    // prologue: G0 = {A0, B0}, G1 = {A1}
    loadB(0, 0);
    loadA(0, 0);
    CP_COMMIT();
    loadA(1, 1);
    CP_COMMIT();

    for (int t = 0; t < 24; ++t) {
        const int cg = t / 3;
        const int ky = t - cg * 3;
        CP_WAIT1();
        __syncthreads();
        const int tn = t + 2;
        if (tn < 24) {
            loadA(tn, tn % 3);
            if (tn % 3 == 0) loadB(tn / 3, (tn / 3) & 1);
        }
        CP_COMMIT();

        const unsigned* As = sm32 + (t % 3) * 6144;
        const unsigned* Bs = sm32 + 18432 + (cg & 1) * 4224;
        const int kyo = ky * 528;

#pragma unroll
        for (int kx = 0; kx < 3; ++kx) {
            uint32_t ah[4][4], al[4][4];
#pragma unroll
            for (int mt = 0; mt < 4; mt++) {
                if (!TAIL || mt < mtN) {
                    int ab = (kx * 8 + mb0 + mt) * 128 + lane4;
                    *(uint4*)ah[mt] = *(const uint4*)(As + ab);
                    *(uint4*)al[mt] = *(const uint4*)(As + ab + 3072);
                }
            }
            uint32_t bh[4][2], bl[4][2];
#pragma unroll
            for (int nf = 0; nf < 4; nf++) {
                int off = nbase[nf] + kyo + kx * 8;
                *(uint2*)bh[nf] = *(const uint2*)(Bs + off);
                *(uint2*)bl[nf] = *(const uint2*)(Bs + off + 2112);
            }
#pragma unroll
            for (int nf = 0; nf < 4; nf++)
#pragma unroll
                for (int mt = 0; mt < 4; mt++)
                    if (!TAIL || mt < mtN) MMA_BF16(d[mt][nf], ah[mt], bh[nf]);
#pragma unroll
            for (int nf = 0; nf < 4; nf++)
#pragma unroll
                for (int mt = 0; mt < 4; mt++)
                    if (!TAIL || mt < mtN) MMA_BF16(d[mt][nf], ah[mt], bl[nf]);
#pragma unroll
            for (int nf = 0; nf < 4; nf++)
#pragma unroll
                for (int mt = 0; mt < 4; mt++)
                    if (!TAIL || mt < mtN) MMA_BF16(d[mt][nf], al[mt], bh[nf]);
        }
    }

    if (!TAIL) {
        // ---- split-output epilogue (+ optional fused SE pooling) ----
        unsigned* outu = (unsigned*)outp;
        float ch0[4], ch1[4];
#pragma unroll
        for (int mt = 0; mt < 4; mt++) { ch0[mt] = 0.f; ch1[mt] = 0.f; }
#pragma unroll
        for (int mt = 0; mt < 4; mt++) {
            const int co0 = m0 + mt * 16 + grp;       // p = grp (0..7)
            const int g = co0 >> 4;
            const int q = 2 * (grp & 3) + (grp >> 2);
            const float bv0 = bias[co0], bv1 = bias[co0 + 8];
            const size_t bhi = (((size_t)b * 8 + g) * 2 + 0) * 131072;
            const size_t blo = bhi + 131072;
#pragma unroll
            for (int nf = 0; nf < 4; nf++) {
                const int n = n0 + nf * 8 + 2 * tid4;
                const int pix = (y0 + (n >> 6)) * 128 + x0 + (n & 63);
                float v0 = d[mt][nf][0] + bv0, v1 = d[mt][nf][1] + bv0;
                float v2 = d[mt][nf][2] + bv1, v3 = d[mt][nf][3] + bv1;
                if (doRelu) {
                    v0 = fmaxf(v0, 0.f); v1 = fmaxf(v1, 0.f);
                    v2 = fmaxf(v2, 0.f); v3 = fmaxf(v3, 0.f);
                }
                ch0[mt] += v0 + v1;
                ch1[mt] += v2 + v3;
                uint32_t h0, l0, h1, l1, h2, l2, h3, l3;
                split2(v0, h0, l0); split2(v1, h1, l1);
                split2(v2, h2, l2); split2(v3, h3, l3);
                outu[bhi + (size_t)pix * 8 + q]       = h0 | (h2 << 16);
                outu[bhi + (size_t)(pix + 1) * 8 + q] = h1 | (h3 << 16);
                outu[blo + (size_t)pix * 8 + q]       = l0 | (l2 << 16);
                outu[blo + (size_t)(pix + 1) * 8 + q] = l1 | (l3 << 16);
            }
        }
        if (seMean) {
            __syncthreads();                     // smem free for reuse
            float* cs = (float*)sm32;
            if (tid < 128) cs[tid] = 0.f;
            __syncthreads();
#pragma unroll
            for (int mt = 0; mt < 4; mt++) {
                float s0 = ch0[mt], s1 = ch1[mt];
                s0 += __shfl_xor_sync(0xffffffffu, s0, 1);
                s0 += __shfl_xor_sync(0xffffffffu, s0, 2);
                s1 += __shfl_xor_sync(0xffffffffu, s1, 1);
                s1 += __shfl_xor_sync(0xffffffffu, s1, 2);
                if (tid4 == 0) {
                    const int co0 = m0 + mt * 16 + grp;
                    atomicAdd(&cs[co0], s0);
                    atomicAdd(&cs[co0 + 8], s1);
                }
            }
            __syncthreads();
            if (tid < 128) atomicAdd(seMean + b * 128 + tid, cs[tid]);
        }
    } else {
        // ---- fused dynamic-filtering epilogue ----
        float* smf = (float*)sm32;               // wgt_s[72][132] @0, kb @9504
        __syncthreads();                         // done with A/B smem
#pragma unroll
        for (int mt = 0; mt < 4; mt++) {
            if (mt >= mtN) continue;
            const int co0 = m0 + mt * 16 + grp;
            const int co1 = co0 + 8;
            const float bv0 = (co0 < 72) ? bias[co0] : 0.f;
            const float bv1 = (co1 < 72) ? bias[co1] : 0.f;
#pragma unroll
            for (int nf = 0; nf < 4; nf++) {
                const int n = n0 + nf * 8 + 2 * tid4;
                const int px = (n >> 6) * 64 + (n & 63);
                if (co0 < 72) {
                    smf[co0 * 132 + px]     = d[mt][nf][0] + bv0;
                    smf[co0 * 132 + px + 1] = d[mt][nf][1] + bv0;
                }
                if (co1 < 72) {
                    smf[co1 * 132 + px]     = d[mt][nf][2] + bv1;
                    smf[co1 * 132 + px + 1] = d[mt][nf][3] + bv1;
                }
            }
        }
        for (int i = tid; i < 1800; i += 256) smf[9504 + i] = basis[i];
        __syncthreads();
        if (tid < 128) {
            const int y = y0 + (tid >> 6);
            const int x = x0 + (tid & 63);
            float e[25];
#pragma unroll
            for (int p = 0; p < 25; p++) e[p] = 0.f;
            for (int k = 0; k < 72; k++) {
                float wv = smf[k * 132 + tid];
                const float* kb = &smf[9504 + k * 25];
#pragma unroll
                for (int p = 0; p < 25; p++) e[p] = fmaf(wv, kb[p], e[p]);
            }
#pragma unroll
            for (int c = 0; c < 3; c++) {
                float acc = 0.f;
#pragma unroll
                for (int dy = 0; dy < 5; dy++) {
                    int yy = y + dy - 2;
                    yy = (yy < 0) ? -yy : ((yy > 127) ? 254 - yy : yy);
                    const float* xr = &xin[((b * 3 + c) * 128 + yy) * 128];
#pragma unroll
                    for (int dx = 0; dx < 5; dx++) {
                        int xx = x + dx - 2;
                        xx = (xx < 0) ? -xx : ((xx > 127) ? 254 - xx : xx);
                        acc = fmaf(e[dy * 5 + dx], xr[xx], acc);
                    }
                }
                outF[((b * 3 + c) * 128 + y) * 128 + x] = acc;
            }
        }
    }
}

// ---------------------------------------------------------------------------
// fp32 head conv (Cin=3, Cout=128), writes the q-ordered SPLIT layout.
// ---------------------------------------------------------------------------
__global__ __launch_bounds__(256, 2)
void conv3x3_head_kernel(const float* __restrict__ in, const float* __restrict__ w,
                         const float* __restrict__ bias, unsigned* __restrict__ out)
{
    const int Cin = 3;
    __shared__ float s_in[3 * 18 * 18];
    __shared__ float s_w[32 * 3 * 9];
    const int tid = threadIdx.x;
    const int b   = blockIdx.z;
    const int coG = blockIdx.y;
    const int ty  = blockIdx.x >> 3;
    const int tx  = blockIdx.x & 7;
    const int y0 = ty * 16, x0 = tx * 16;
    const int co_base = tid >> 5;              // 0..7 = p
    const int pid = tid & 31;
    const int y  = pid >> 1;
    const int xb = (pid & 1) * 8;

    float acc[4][8];
#pragma unroll
    for (int j = 0; j < 4; j++)
#pragma unroll
        for (int p = 0; p < 8; p++) acc[j][p] = 0.f;

    for (int idx = tid; idx < 3 * 324; idx += 256) {
        int ci = idx / 324;
        int r  = idx - ci * 324;
        int iy = r / 18, ix = r - iy * 18;
        int gy = y0 - 1 + iy, gx = x0 - 1 + ix;
        float v = 0.f;
        if ((unsigned)gy < 128u && (unsigned)gx < 128u)
            v = in[((b * Cin + ci) * 128 + gy) * 128 + gx];
        s_in[idx] = v;
    }
    for (int idx = tid; idx < 32 * 27; idx += 256) {
        int l = idx / 27;
        int r = idx - l * 27;
        s_w[idx] = w[(coG * 32 + l) * 27 + r];
    }
    __syncthreads();

#pragma unroll
    for (int ci = 0; ci < 3; ci++) {
#pragma unroll
        for (int ky = 0; ky < 3; ky++) {
            float r[10];
            const float* row = &s_in[ci * 324 + (y + ky) * 18 + xb];
#pragma unroll
            for (int i = 0; i < 10; i++) r[i] = row[i];
#pragma unroll
            for (int kx = 0; kx < 3; kx++) {
#pragma unroll
                for (int j = 0; j < 4; j++) {
                    float wv = s_w[(co_base + j * 8) * 27 + ci * 9 + ky * 3 + kx];
#pragma unroll
                    for (int p = 0; p < 8; p++)
                        acc[j][p] = fmaf(wv, r[p + kx], acc[j][p]);
                }
            }
        }
    }

    float bv[4];
#pragma unroll
    for (int j = 0; j < 4; j++) bv[j] = bias[coG * 32 + co_base + j * 8];

    const int q = 2 * (co_base & 3) + (co_base >> 2);
    const int g0 = 2 * coG, g1 = 2 * coG + 1;
    const size_t b0h = (((size_t)b * 8 + g0) * 2 + 0) * 131072;
    const size_t b1h = (((size_t)b * 8 + g1) * 2 + 0) * 131072;
#pragma unroll
    for (int p = 0; p < 8; p++) {
        size_t pix8 = (size_t)((y0 + y) * 128 + x0 + xb + p) * 8 + q;
        uint32_t h0, q0, h1, q1, h2, q2, h3, q3;
        split2(acc[0][p] + bv[0], h0, q0);
        split2(acc[1][p] + bv[1], h1, q1);
        split2(acc[2][p] + bv[2], h2, q2);
        split2(acc[3][p] + bv[3], h3, q3);
        out[b0h + pix8]          = h0 | (h1 << 16);
        out[b0h + 131072 + pix8] = q0 | (q1 << 16);
        out[b1h + pix8]          = h2 | (h3 << 16);
        out[b1h + 131072 + pix8] = q2 | (q3 << 16);
    }
}

// ---------------------------------------------------------------------------
// SE fc: mean (unnormalized sums) -> scl. Applies 1/16384 on load.
// 1 block, 1024 threads.
// ---------------------------------------------------------------------------
__global__ void se_fc_kernel(const float* __restrict__ mean,
                             const float* __restrict__ w1, const float* __restrict__ b1,
                             const float* __restrict__ w2, const float* __restrict__ b2,
                             float* __restrict__ scl)
{
    __shared__ float smn[8][128];
    __shared__ float s1[8][8];
    int t = threadIdx.x;
    smn[t >> 7][t & 127] = mean[t] * (1.f / 16384.f);
    __syncthreads();
    if (t < 64) {
        int bb = t >> 3, j = t & 7;
        float a = b1[j];
#pragma unroll 4
        for (int c = 0; c < 128; c++) a = fmaf(w1[j * 128 + c], smn[bb][c], a);
        s1[bb][j] = fmaxf(a, 0.f);
    }
    __syncthreads();
    int bb = t >> 7, co = t & 127;
    float a = b2[co];
#pragma unroll
    for (int j = 0; j < 8; j++) a = fmaf(w2[co * 8 + j], s1[bb][j], a);
    scl[t] = 1.f / (1.f + expf(-a));
}

// ---------------------------------------------------------------------------
extern "C" void kernel_launch(void* const* d_in, const int* in_sizes, int n_in,
                              void* d_out, int out_size)
{
    const float* x      = (const float*)d_in[0];
    const float* w_head = (const float*)d_in[1];
    const float* b_head = (const float*)d_in[2];
    const float* w_h1a  = (const float*)d_in[3];
    const float* b_h1a  = (const float*)d_in[4];
    const float* w_h1b  = (const float*)d_in[5];
    const float* b_h1b  = (const float*)d_in[6];
    const float* du1_w1 = (const float*)d_in[7];
    const float* du1_b1 = (const float*)d_in[8];
    const float* du1_w2 = (const float*)d_in[9];
    const float* du1_b2 = (const float*)d_in[10];
    const float* w_h2a  = (const float*)d_in[11];
    const float* b_h2a  = (const float*)d_in[12];
    const float* w_h2b  = (const float*)d_in[13];
    const float* b_h2b  = (const float*)d_in[14];
    const float* du2_w1 = (const float*)d_in[15];
    const float* du2_b1 = (const float*)d_in[16];
    const float* du2_w2 = (const float*)d_in[17];
    const float* du2_b2 = (const float*)d_in[18];
    const float* w_tail = (const float*)d_in[19];
    const float* b_tail = (const float*)d_in[20];
    const float* basis  = (const float*)d_in[21];

    unsigned *A, *Bb, *Wt, *Wts;
    float *mean1, *mean2, *scl;
    cudaGetSymbolAddress((void**)&A,     g_A);
    cudaGetSymbolAddress((void**)&Bb,    g_B);
    cudaGetSymbolAddress((void**)&mean1, g_mean1);
    cudaGetSymbolAddress((void**)&mean2, g_mean2);
    cudaGetSymbolAddress((void**)&scl,   g_scl);
    cudaGetSymbolAddress((void**)&Wt,    g_Wt);
    cudaGetSymbolAddress((void**)&Wts,   g_Wts);

    cudaFuncSetAttribute(conv_mma_kernel<false>,
                         cudaFuncAttributeMaxDynamicSharedMemorySize, CONV_SMEM);
    cudaFuncSetAttribute(conv_mma_kernel<true>,
                         cudaFuncAttributeMaxDynamicSharedMemorySize, CONV_SMEM);

    dim3 cgrid(128, B_);
    // 0: all repacks in one launch (+ zero SE mean buffers)
    repack_all_kernel<<<dim3(576, 5), 128>>>(w_h1a, w_h1b, w_h2a, w_h2b, w_tail, Wt,
                                             mean1, mean2);
    // 1: head (fp32, Cin=3) -> q-ordered split planes in g_A
    conv3x3_head_kernel<<<dim3(64, 4, B_), 256>>>(x, w_head, b_head, A);
    // 2: conv h1a
    conv_mma_kernel<false><<<cgrid, 256, CONV_SMEM>>>(
        A, Wt + 0 * WS, b_h1a, Bb, 128, 1, 0, nullptr, nullptr, nullptr, nullptr);
    // 3: conv h1b (+ fused SE1 pooling)  <-- ncu captures this launch
    conv_mma_kernel<false><<<cgrid, 256, CONV_SMEM>>>(
        Bb, Wt + 1 * WS, b_h1b, A, 128, 1, 0, mean1, nullptr, nullptr, nullptr);
    // SE 1 fc -> scaled weights for h2a
    se_fc_kernel<<<1, 1024>>>(mean1, du1_w1, du1_b1, du1_w2, du1_b2, scl);
    scale_w_kernel<<<dim3(576, B_), 128>>>(Wt + 2 * WS, scl, Wts);
    // block 2
    conv_mma_kernel<false><<<cgrid, 256, CONV_SMEM>>>(
        A, Wts, b_h2a, Bb, 128, 1, 1, nullptr, nullptr, nullptr, nullptr);
    conv_mma_kernel<false><<<cgrid, 256, CONV_SMEM>>>(
        Bb, Wt + 3 * WS, b_h2b, A, 128, 1, 0, mean2, nullptr, nullptr, nullptr);
    // SE 2 fc -> scaled weights for tail
    se_fc_kernel<<<1, 1024>>>(mean2, du2_w1, du2_b1, du2_w2, du2_b2, scl);
    scale_w_kernel<<<dim3(576, B_), 128>>>(Wt + 4 * WS, scl, Wts);
    // tail conv + fused dynamic filtering -> d_out
    conv_mma_kernel<true><<<cgrid, 256, CONV_SMEM>>>(
        A, Wts, b_tail, nullptr, 72, 0, 1, nullptr, x, basis, (float*)d_out);
}

// round 17
// speedup vs baseline: 1.1419x; 1.0161x over previous
#include <cuda_runtime.h>
#include <cuda_bf16.h>
#include <math.h>
#include <cstdint>

// ===========================================================================
// DARM on GB300 (base sm_103 ISA): split-bf16 (3-term) mma.sync implicit-GEMM
// convs + fp32 head conv (split-output) + fused SE + fused dyn filtering.
// B=8, C=3, H=W=128, F=128, S=8, K=72.
// Activation layout (load-native): act[b][g][pl][y][x][q], q=0..7,
//   word q = packed(bf16 ci0 | bf16 ci1<<16), ci0=g*16+p, ci1=ci0+8,
//   p=(q>>1)+((q&1)<<2), pl = hi/lo split plane.
// R17: (1) se_fc folded into scale_w (per-block redundant squeeze FC);
//      (2) conv main loop unrolled x6 -> all smem offsets compile-time
//          (kills the t/3, t%3 address ALU in the hot loop).
// ===========================================================================

#define B_ 8
#define F_ 128
#define K_ 72
#define WS 147456         // words per repacked conv weight set (24 * 6144)

__device__ unsigned g_A[16777216];           // 64 MiB  (split act / ping)
__device__ unsigned g_B[16777216];           // 64 MiB  (split act / pong)
__device__ float    g_mean1[B_ * F_];
__device__ float    g_mean2[B_ * F_];
__device__ unsigned g_Wt[5 * WS];            // fragment-major repacked weights
__device__ unsigned g_Wts[B_ * WS];          // per-batch SE-scaled weights

// ---------------------------------------------------------------------------
// helpers
// ---------------------------------------------------------------------------
__device__ __forceinline__ uint32_t smem_u32(const void* p) {
    uint32_t a;
    asm("{ .reg .u64 t; cvta.to.shared.u64 t, %1; cvt.u32.u64 %0, t; }" : "=r"(a) : "l"(p));
    return a;
}
__device__ __forceinline__ void cpa16(uint32_t d, const void* s) {
    asm volatile("cp.async.cg.shared.global [%0], [%1], 16;" :: "r"(d), "l"(s) : "memory");
}
__device__ __forceinline__ void cpa16z(uint32_t d, const void* s, int sz) {
    asm volatile("cp.async.cg.shared.global [%0], [%1], 16, %2;" :: "r"(d), "l"(s), "r"(sz) : "memory");
}
#define CP_COMMIT() asm volatile("cp.async.commit_group;" ::: "memory")
#define CP_WAIT1()  asm volatile("cp.async.wait_group 1;" ::: "memory")

#define MMA_BF16(d, a, bb) \
    asm volatile("mma.sync.aligned.m16n8k16.row.col.f32.bf16.bf16.f32 " \
        "{%0,%1,%2,%3},{%4,%5,%6,%7},{%8,%9},{%0,%1,%2,%3};" \
        : "+f"((d)[0]), "+f"((d)[1]), "+f"((d)[2]), "+f"((d)[3]) \
        : "r"((a)[0]), "r"((a)[1]), "r"((a)[2]), "r"((a)[3]), "r"((bb)[0]), "r"((bb)[1]))

__device__ __forceinline__ uint32_t bfb(float v) {
    return (uint32_t)__bfloat16_as_ushort(__float2bfloat16(v));
}
__device__ __forceinline__ float bff(uint32_t b) { return __uint_as_float(b << 16); }
__device__ __forceinline__ void split2(float v, uint32_t& h, uint32_t& l) {
    h = bfb(v);
    l = bfb(v - bff(h));
}

// ---------------------------------------------------------------------------
// Weight repack (ALL 5 convs, fragment-major) + zero the SE mean buffers.
// grid (576, 5), block 128.
// ---------------------------------------------------------------------------
__global__ void repack_all_kernel(const float* __restrict__ w0, const float* __restrict__ w1,
                                  const float* __restrict__ w2, const float* __restrict__ w3,
                                  const float* __restrict__ w4, unsigned* __restrict__ wt,
                                  float* __restrict__ mean1, float* __restrict__ mean2)
{
    if (blockIdx.y == 0 && blockIdx.x < 8) {
        int i = blockIdx.x * 128 + threadIdx.x;
        mean1[i] = 0.f;
        mean2[i] = 0.f;
    }
    const float* w;
    int Cout = 128;
    switch (blockIdx.y) {
        case 0: w = w0; break;
        case 1: w = w1; break;
        case 2: w = w2; break;
        case 3: w = w3; break;
        default: w = w4; Cout = 72; break;
    }
    int idx = blockIdx.x * 128 + threadIdx.x;        // 0..73727
    int w_   = idx & 3;
    int lane = (idx >> 2) & 31;
    int mblk = (idx >> 7) & 7;
    int rest = idx >> 10;                            // t*3 + kx
    int kx = rest % 3;
    int t  = rest / 3;
    int cg = t / 3, ky = t - cg * 3;
    int p  = (lane & 3) + ((w_ >> 1) << 2);
    int co = mblk * 16 + (lane >> 2) + ((w_ & 1) << 3);
    int ci0 = cg * 16 + p, ci1 = ci0 + 8;
    float v0 = 0.f, v1 = 0.f;
    if (co < Cout) {
        v0 = w[co * 1152 + ci0 * 9 + ky * 3 + kx];
        v1 = w[co * 1152 + ci1 * 9 + ky * 3 + kx];
    }
    uint32_t h0, l0, h1, l1;
    split2(v0, h0, l0); split2(v1, h1, l1);
    unsigned* o = wt + (size_t)blockIdx.y * WS + t * 6144;
    int base = (kx * 8 + mblk) * 128 + lane * 4 + w_;
    o[base]        = h0 | (h1 << 16);
    o[base + 3072] = l0 | (l1 << 16);
}

// ---------------------------------------------------------------------------
// SE scale_w with fused squeeze-FC: mean (unnormalized sums) -> scl (per
// block, redundant but cheap, bitwise-identical to the old se_fc) -> scaled
// per-batch weights. grid (576, 8), block 128.
// ---------------------------------------------------------------------------
__global__ void scale_w_kernel(const unsigned* __restrict__ wt,
                               const float* __restrict__ mean,
                               const float* __restrict__ w1, const float* __restrict__ b1,
                               const float* __restrict__ w2, const float* __restrict__ b2,
                               unsigned* __restrict__ wts)
{
    __shared__ float smn[128];
    __shared__ float s1[8];
    const int b = blockIdx.y;
    const int tt = threadIdx.x;
    smn[tt] = mean[b * 128 + tt] * (1.f / 16384.f);
    __syncthreads();
    if (tt < 8) {
        float a = b1[tt];
#pragma unroll 4
        for (int c = 0; c < 128; c++) a = fmaf(w1[tt * 128 + c], smn[c], a);
        s1[tt] = fmaxf(a, 0.f);
    }
    __syncthreads();

    int idx = blockIdx.x * 128 + tt;
    int w_   = idx & 3;
    int lane = (idx >> 2) & 31;
    int mblk = (idx >> 7) & 7;
    int rest = idx >> 10;
    int kx = rest % 3;
    int t  = rest / 3;
    int cg = t / 3;
    int p  = (lane & 3) + ((w_ >> 1) << 2);
    int ci0 = cg * 16 + p, ci1 = ci0 + 8;

    float a0 = b2[ci0], a1 = b2[ci1];
#pragma unroll
    for (int j = 0; j < 8; j++) {
        a0 = fmaf(w2[ci0 * 8 + j], s1[j], a0);
        a1 = fmaf(w2[ci1 * 8 + j], s1[j], a1);
    }
    float s0 = 1.f / (1.f + expf(-a0));
    float s1v = 1.f / (1.f + expf(-a1));

    int base = t * 6144 + (kx * 8 + mblk) * 128 + lane * 4 + w_;
    unsigned wh = wt[base], wl = wt[base + 3072];
    float v0 = (bff(wh & 0xffffu) + bff(wl & 0xffffu)) * s0;
    float v1 = (bff(wh >> 16) + bff(wl >> 16)) * s1v;
    uint32_t h0, l0, h1, l1;
    split2(v0, h0, l0); split2(v1, h1, l1);
    unsigned* o = wts + (size_t)b * WS;
    o[base]        = h0 | (h1 << 16);
    o[base + 3072] = l0 | (l1 << 16);
}

// ---------------------------------------------------------------------------
// split-bf16 mma conv, Cin=128. CTA: M=128 co x N=128 px (2 rows x 64 cols).
// 8 warps (2m x 4n), warp tile 64x32 -> mt<=4, nf=4 m16n8k16 frags.
// K = 1152: 24 chunks, main loop unrolled x6 (u%3, (u/3)&1 constants).
// TAIL=false: mb0=hi*4, mtN=4; splitOut epilogue + optional fused SE pool.
// TAIL=true (Cout=72): balanced {0..2 | 3..4}; fused dynamic filtering.
// smem b32: A bufs 3 x 6144 @ 0, B bufs 2 x 4224 @ 18432.
// Pipeline: 2-chunk slack, wait_group 1, one commit per iteration.
// grid (128, 8), block 256, 2 CTAs/SM.
// ---------------------------------------------------------------------------
#define CONV_SMEM ((3 * 6144 + 2 * 4224) * 4)   // 107520 B

template <bool TAIL>
__global__ __launch_bounds__(256, 2)
void conv_mma_kernel(const unsigned* __restrict__ actin, const unsigned* __restrict__ wt,
                     const float* __restrict__ bias, void* __restrict__ outp,
                     int Cout, int doRelu, int perBatchW,
                     float* __restrict__ seMean,
                     const float* __restrict__ xin, const float* __restrict__ basis,
                     float* __restrict__ outF)
{
    extern __shared__ unsigned sm32[];
    const uint32_t sb = smem_u32(sm32);

    const int tid  = threadIdx.x;
    const int wid  = tid >> 5;                  // 0..7
    const int lane = tid & 31;
    const int tid4 = lane & 3;
    const int grp  = lane >> 2;
    const int hi   = wid >> 2;                  // 0 = lower-m, 1 = upper-m
    const int n0 = (wid & 3) * 32;              // 0..96
    const int lane4 = lane * 4;
    const int mb0 = TAIL ? (hi ? 3 : 0) : hi * 4;
    const int mtN = TAIL ? (hi ? 2 : 3) : 4;
    const int m0  = mb0 * 16;
    const int b  = blockIdx.y;
    const int rp = blockIdx.x >> 1;             // row-pair 0..63
    const int ch = blockIdx.x & 1;              // col-half
    const int y0 = rp * 2;
    const int x0 = ch * 64;

    const unsigned* wtb = wt + (perBatchW ? (size_t)b * WS : 0);

    int nbase[4];
#pragma unroll
    for (int nf = 0; nf < 4; nf++) {
        int n = n0 + nf * 8 + grp;
        nbase[nf] = (n >> 6) * 528 + (n & 63) * 8 + tid4 * 2;
    }

    float d[4][4][4];
#pragma unroll
    for (int mt = 0; mt < 4; mt++)
#pragma unroll
        for (int nf = 0; nf < 4; nf++)
#pragma unroll
            for (int i = 0; i < 4; i++) d[mt][nf][i] = 0.f;

    auto loadA = [&](int t, int buf) {
        const unsigned* src = wtb + t * 6144;
        const uint32_t dst = sb + (uint32_t)buf * 24576u;
#pragma unroll
        for (int i = tid; i < 1536; i += 256)
            cpa16(dst + (uint32_t)i * 16u, src + i * 4);
    };
    auto loadB = [&](int cg, int buf) {
        const uint32_t dst = sb + 73728u + (buf ? 16896u : 0u);
        const unsigned* basep = actin + ((size_t)b * 8 + cg) * 262144;
        for (int i = tid; i < 1056; i += 256) {
            int qh = i & 1, r = i >> 1;          // r = (pl*4+rs)*66 + xs
            int xs = r % 66;
            int r2 = r / 66;                     // pl*4 + rs
            int rs = r2 & 3, pl = r2 >> 2;
            int y = y0 - 1 + rs, xi = x0 - 1 + xs;
            bool ok = ((unsigned)y < 128u) && ((unsigned)xi < 128u);
            const unsigned* src = basep + pl * 131072
                                + (ok ? ((y * 128 + xi) * 8) : 0) + qh * 4;
            uint32_t doff = (uint32_t)(pl * 2112 + rs * 528 + xs * 8 + qh * 4) * 4u;
            cpa16z(dst + doff, src, ok ? 16 : 0);
        }
    };

    // prologue: G0 = {A0, B0}, G1 = {A1}
    loadB(0, 0);
    loadA(0, 0);
    CP_COMMIT();
    loadA(1, 1);
    CP_COMMIT();

    for (int tt = 0; tt < 4; ++tt) {
#pragma unroll
        for (int u = 0; u < 6; ++u) {
            const int t = tt * 6 + u;
            // compile-time: abuf = u%3, bbuf = (u/3)&1, ky = u%3
            constexpr_helper:;
            CP_WAIT1();
            __syncthreads();
            const int tn = t + 2;
            if (tn < 24) {
                loadA(tn, (u + 2) % 3);
                if ((u + 2) % 3 == 0) loadB(tn / 3, ((u + 2) / 3 + 2 * 0 + (tt * 2)) & 1);
            }
            CP_COMMIT();

            const unsigned* As = sm32 + (u % 3) * 6144;
            const unsigned* Bs = sm32 + 18432 + ((u / 3) & 1) * 4224;
            const int kyo = (u % 3) * 528;

#pragma unroll
            for (int kx = 0; kx < 3; ++kx) {
                uint32_t ah[4][4], al[4][4];
#pragma unroll
                for (int mt = 0; mt < 4; mt++) {
                    if (!TAIL || mt < mtN) {
                        int ab = (kx * 8 + mb0 + mt) * 128 + lane4;
                        *(uint4*)ah[mt] = *(const uint4*)(As + ab);
                        *(uint4*)al[mt] = *(const uint4*)(As + ab + 3072);
                    }
                }
                uint32_t bh[4][2], bl[4][2];
#pragma unroll
                for (int nf = 0; nf < 4; nf++) {
                    int off = nbase[nf] + kyo + kx * 8;
                    *(uint2*)bh[nf] = *(const uint2*)(Bs + off);
                    *(uint2*)bl[nf] = *(const uint2*)(Bs + off + 2112);
                }
#pragma unroll
                for (int nf = 0; nf < 4; nf++)
#pragma unroll
                    for (int mt = 0; mt < 4; mt++)
                        if (!TAIL || mt < mtN) MMA_BF16(d[mt][nf], ah[mt], bh[nf]);
#pragma unroll
                for (int nf = 0; nf < 4; nf++)
#pragma unroll
                    for (int mt = 0; mt < 4; mt++)
                        if (!TAIL || mt < mtN) MMA_BF16(d[mt][nf], ah[mt], bl[nf]);
#pragma unroll
                for (int nf = 0; nf < 4; nf++)
#pragma unroll
                    for (int mt = 0; mt < 4; mt++)
                        if (!TAIL || mt < mtN) MMA_BF16(d[mt][nf], al[mt], bh[nf]);
            }
        }
    }

    if (!TAIL) {
        // ---- split-output epilogue (+ optional fused SE pooling) ----
        unsigned* outu = (unsigned*)outp;
        float ch0[4], ch1[4];
#pragma unroll
        for (int mt = 0; mt < 4; mt++) { ch0[mt] = 0.f; ch1[mt] = 0.f; }
#pragma unroll
        for (int mt = 0; mt < 4; mt++) {
            const int co0 = m0 + mt * 16 + grp;       // p = grp (0..7)
            const int g = co0 >> 4;
            const int q = 2 * (grp & 3) + (grp >> 2);
            const float bv0 = bias[co0], bv1 = bias[co0 + 8];
            const size_t bhi = (((size_t)b * 8 + g) * 2 + 0) * 131072;
            const size_t blo = bhi + 131072;
#pragma unroll
            for (int nf = 0; nf < 4; nf++) {
                const int n = n0 + nf * 8 + 2 * tid4;
                const int pix = (y0 + (n >> 6)) * 128 + x0 + (n & 63);
                float v0 = d[mt][nf][0] + bv0, v1 = d[mt][nf][1] + bv0;
                float v2 = d[mt][nf][2] + bv1, v3 = d[mt][nf][3] + bv1;
                if (doRelu) {
                    v0 = fmaxf(v0, 0.f); v1 = fmaxf(v1, 0.f);
                    v2 = fmaxf(v2, 0.f); v3 = fmaxf(v3, 0.f);
                }
                ch0[mt] += v0 + v1;
                ch1[mt] += v2 + v3;
                uint32_t h0, l0, h1, l1, h2, l2, h3, l3;
                split2(v0, h0, l0); split2(v1, h1, l1);
                split2(v2, h2, l2); split2(v3, h3, l3);
                outu[bhi + (size_t)pix * 8 + q]       = h0 | (h2 << 16);
                outu[bhi + (size_t)(pix + 1) * 8 + q] = h1 | (h3 << 16);
                outu[blo + (size_t)pix * 8 + q]       = l0 | (l2 << 16);
                outu[blo + (size_t)(pix + 1) * 8 + q] = l1 | (l3 << 16);
            }
        }
        if (seMean) {
            __syncthreads();                     // smem free for reuse
            float* cs = (float*)sm32;
            if (tid < 128) cs[tid] = 0.f;
            __syncthreads();
#pragma unroll
            for (int mt = 0; mt < 4; mt++) {
                float s0 = ch0[mt], s1 = ch1[mt];
                s0 += __shfl_xor_sync(0xffffffffu, s0, 1);
                s0 += __shfl_xor_sync(0xffffffffu, s0, 2);
                s1 += __shfl_xor_sync(0xffffffffu, s1, 1);
                s1 += __shfl_xor_sync(0xffffffffu, s1, 2);
                if (tid4 == 0) {
                    const int co0 = m0 + mt * 16 + grp;
                    atomicAdd(&cs[co0], s0);
                    atomicAdd(&cs[co0 + 8], s1);
                }
            }
            __syncthreads();
            if (tid < 128) atomicAdd(seMean + b * 128 + tid, cs[tid]);
        }
    } else {
        // ---- fused dynamic-filtering epilogue ----
        float* smf = (float*)sm32;               // wgt_s[72][132] @0, kb @9504
        __syncthreads();                         // done with A/B smem
#pragma unroll
        for (int mt = 0; mt < 4; mt++) {
            if (mt >= mtN) continue;
            const int co0 = m0 + mt * 16 + grp;
            const int co1 = co0 + 8;
            const float bv0 = (co0 < 72) ? bias[co0] : 0.f;
            const float bv1 = (co1 < 72) ? bias[co1] : 0.f;
#pragma unroll
            for (int nf = 0; nf < 4; nf++) {
                const int n = n0 + nf * 8 + 2 * tid4;
                const int px = (n >> 6) * 64 + (n & 63);
                if (co0 < 72) {
                    smf[co0 * 132 + px]     = d[mt][nf][0] + bv0;
                    smf[co0 * 132 + px + 1] = d[mt][nf][1] + bv0;
                }
                if (co1 < 72) {
                    smf[co1 * 132 + px]     = d[mt][nf][2] + bv1;
                    smf[co1 * 132 + px + 1] = d[mt][nf][3] + bv1;
                }
            }
        }
        for (int i = tid; i < 1800; i += 256) smf[9504 + i] = basis[i];
        __syncthreads();
        if (tid < 128) {
            const int y = y0 + (tid >> 6);
            const int x = x0 + (tid & 63);
            float e[25];
#pragma unroll
            for (int p = 0; p < 25; p++) e[p] = 0.f;
            for (int k = 0; k < 72; k++) {
                float wv = smf[k * 132 + tid];
                const float* kb = &smf[9504 + k * 25];
#pragma unroll
                for (int p = 0; p < 25; p++) e[p] = fmaf(wv, kb[p], e[p]);
            }
#pragma unroll
            for (int c = 0; c < 3; c++) {
                float acc = 0.f;
#pragma unroll
                for (int dy = 0; dy < 5; dy++) {
                    int yy = y + dy - 2;
                    yy = (yy < 0) ? -yy : ((yy > 127) ? 254 - yy : yy);
                    const float* xr = &xin[((b * 3 + c) * 128 + yy) * 128];
#pragma unroll
                    for (int dx = 0; dx < 5; dx++) {
                        int xx = x + dx - 2;
                        xx = (xx < 0) ? -xx : ((xx > 127) ? 254 - xx : xx);
                        acc = fmaf(e[dy * 5 + dx], xr[xx], acc);
                    }
                }
                outF[((b * 3 + c) * 128 + y) * 128 + x] = acc;
            }
        }
    }
}

// ---------------------------------------------------------------------------
// fp32 head conv (Cin=3, Cout=128), writes the q-ordered SPLIT layout.
// ---------------------------------------------------------------------------
__global__ __launch_bounds__(256, 2)
void conv3x3_head_kernel(const float* __restrict__ in, const float* __restrict__ w,
                         const float* __restrict__ bias, unsigned* __restrict__ out)
{
    const int Cin = 3;
    __shared__ float s_in[3 * 18 * 18];
    __shared__ float s_w[32 * 3 * 9];
    const int tid = threadIdx.x;
    const int b   = blockIdx.z;
    const int coG = blockIdx.y;
    const int ty  = blockIdx.x >> 3;
    const int tx  = blockIdx.x & 7;
    const int y0 = ty * 16, x0 = tx * 16;
    const int co_base = tid >> 5;              // 0..7 = p
    const int pid = tid & 31;
    const int y  = pid >> 1;
    const int xb = (pid & 1) * 8;

    float acc[4][8];
#pragma unroll
    for (int j = 0; j < 4; j++)
#pragma unroll
        for (int p = 0; p < 8; p++) acc[j][p] = 0.f;

    for (int idx = tid; idx < 3 * 324; idx += 256) {
        int ci = idx / 324;
        int r  = idx - ci * 324;
        int iy = r / 18, ix = r - iy * 18;
        int gy = y0 - 1 + iy, gx = x0 - 1 + ix;
        float v = 0.f;
        if ((unsigned)gy < 128u && (unsigned)gx < 128u)
            v = in[((b * Cin + ci) * 128 + gy) * 128 + gx];
        s_in[idx] = v;
    }
    for (int idx = tid; idx < 32 * 27; idx += 256) {
        int l = idx / 27;
        int r = idx - l * 27;
        s_w[idx] = w[(coG * 32 + l) * 27 + r];
    }
    __syncthreads();

#pragma unroll
    for (int ci = 0; ci < 3; ci++) {
#pragma unroll
        for (int ky = 0; ky < 3; ky++) {
            float r[10];
            const float* row = &s_in[ci * 324 + (y + ky) * 18 + xb];
#pragma unroll
            for (int i = 0; i < 10; i++) r[i] = row[i];
#pragma unroll
            for (int kx = 0; kx < 3; kx++) {
#pragma unroll
                for (int j = 0; j < 4; j++) {
                    float wv = s_w[(co_base + j * 8) * 27 + ci * 9 + ky * 3 + kx];
#pragma unroll
                    for (int p = 0; p < 8; p++)
                        acc[j][p] = fmaf(wv, r[p + kx], acc[j][p]);
                }
            }
        }
    }

    float bv[4];
#pragma unroll
    for (int j = 0; j < 4; j++) bv[j] = bias[coG * 32 + co_base + j * 8];

    const int q = 2 * (co_base & 3) + (co_base >> 2);
    const int g0 = 2 * coG, g1 = 2 * coG + 1;
    const size_t b0h = (((size_t)b * 8 + g0) * 2 + 0) * 131072;
    const size_t b1h = (((size_t)b * 8 + g1) * 2 + 0) * 131072;
#pragma unroll
    for (int p = 0; p < 8; p++) {
        size_t pix8 = (size_t)((y0 + y) * 128 + x0 + xb + p) * 8 + q;
        uint32_t h0, q0, h1, q1, h2, q2, h3, q3;
        split2(acc[0][p] + bv[0], h0, q0);
        split2(acc[1][p] + bv[1], h1, q1);
        split2(acc[2][p] + bv[2], h2, q2);
        split2(acc[3][p] + bv[3], h3, q3);
        out[b0h + pix8]          = h0 | (h1 << 16);
        out[b0h + 131072 + pix8] = q0 | (q1 << 16);
        out[b1h + pix8]          = h2 | (h3 << 16);
        out[b1h + 131072 + pix8] = q2 | (q3 << 16);
    }
}

// ---------------------------------------------------------------------------
extern "C" void kernel_launch(void* const* d_in, const int* in_sizes, int n_in,
                              void* d_out, int out_size)
{
    const float* x      = (const float*)d_in[0];
    const float* w_head = (const float*)d_in[1];
    const float* b_head = (const float*)d_in[2];
    const float* w_h1a  = (const float*)d_in[3];
    const float* b_h1a  = (const float*)d_in[4];
    const float* w_h1b  = (const float*)d_in[5];
    const float* b_h1b  = (const float*)d_in[6];
    const float* du1_w1 = (const float*)d_in[7];
    const float* du1_b1 = (const float*)d_in[8];
    const float* du1_w2 = (const float*)d_in[9];
    const float* du1_b2 = (const float*)d_in[10];
    const float* w_h2a  = (const float*)d_in[11];
    const float* b_h2a  = (const float*)d_in[12];
    const float* w_h2b  = (const float*)d_in[13];
    const float* b_h2b  = (const float*)d_in[14];
    const float* du2_w1 = (const float*)d_in[15];
    const float* du2_b1 = (const float*)d_in[16];
    const float* du2_w2 = (const float*)d_in[17];
    const float* du2_b2 = (const float*)d_in[18];
    const float* w_tail = (const float*)d_in[19];
    const float* b_tail = (const float*)d_in[20];
    const float* basis  = (const float*)d_in[21];

    unsigned *A, *Bb, *Wt, *Wts;
    float *mean1, *mean2;
    cudaGetSymbolAddress((void**)&A,     g_A);
    cudaGetSymbolAddress((void**)&Bb,    g_B);
    cudaGetSymbolAddress((void**)&mean1, g_mean1);
    cudaGetSymbolAddress((void**)&mean2, g_mean2);
    cudaGetSymbolAddress((void**)&Wt,    g_Wt);
    cudaGetSymbolAddress((void**)&Wts,   g_Wts);

    cudaFuncSetAttribute(conv_mma_kernel<false>,
                         cudaFuncAttributeMaxDynamicSharedMemorySize, CONV_SMEM);
    cudaFuncSetAttribute(conv_mma_kernel<true>,
                         cudaFuncAttributeMaxDynamicSharedMemorySize, CONV_SMEM);

    dim3 cgrid(128, B_);
    // 0: all repacks in one launch (+ zero SE mean buffers)
    repack_all_kernel<<<dim3(576, 5), 128>>>(w_h1a, w_h1b, w_h2a, w_h2b, w_tail, Wt,
                                             mean1, mean2);
    // 1: head (fp32, Cin=3) -> q-ordered split planes in g_A
    conv3x3_head_kernel<<<dim3(64, 4, B_), 256>>>(x, w_head, b_head, A);
    // 2: conv h1a
    conv_mma_kernel<false><<<cgrid, 256, CONV_SMEM>>>(
        A, Wt + 0 * WS, b_h1a, Bb, 128, 1, 0, nullptr, nullptr, nullptr, nullptr);
    // 3: conv h1b (+ fused SE1 pooling)  <-- ncu captures this launch
    conv_mma_kernel<false><<<cgrid, 256, CONV_SMEM>>>(
        Bb, Wt + 1 * WS, b_h1b, A, 128, 1, 0, mean1, nullptr, nullptr, nullptr);
    // SE1 fc + weight scale (fused) -> per-batch weights for h2a
    scale_w_kernel<<<dim3(576, B_), 128>>>(Wt + 2 * WS, mean1,
                                           du1_w1, du1_b1, du1_w2, du1_b2, Wts);
    // block 2
    conv_mma_kernel<false><<<cgrid, 256, CONV_SMEM>>>(
        A, Wts, b_h2a, Bb, 128, 1, 1, nullptr, nullptr, nullptr, nullptr);
    conv_mma_kernel<false><<<cgrid, 256, CONV_SMEM>>>(
        Bb, Wt + 3 * WS, b_h2b, A, 128, 1, 0, mean2, nullptr, nullptr, nullptr);
    // SE2 fc + weight scale (fused) -> per-batch weights for tail
    scale_w_kernel<<<dim3(576, B_), 128>>>(Wt + 4 * WS, mean2,
                                           du2_w1, du2_b1, du2_w2, du2_b2, Wts);
    // tail conv + fused dynamic filtering -> d_out
    conv_mma_kernel<true><<<cgrid, 256, CONV_SMEM>>>(
        A, Wts, b_tail, nullptr, 72, 0, 1, nullptr, x, basis, (float*)d_out);
}